// round 1
// baseline (speedup 1.0000x reference)
#include <cuda_runtime.h>

#define NEGV (-1e30f)

// Problem constants: N=8, C=512, Cq=64, H=W=96
// x: [8,512,96,96] fp32

// ---------------- scratch (device globals; allocation-free) ----------------
__device__ float g_q   [8u*64*9216];    // [n,cq,h,w]
__device__ float g_k   [8u*64*9216];
__device__ float g_qT  [8u*64*9216];    // [n,cq,w,h]
__device__ float g_kT  [8u*64*9216];
__device__ float g_v   [8u*512*9216];   // [n,c,h,w]
__device__ float g_vT  [8u*512*9216];   // [n,c,w,h]
__device__ float g_colT[8u*512*9216];   // [n,c,w,h] (column-attention output, transposed)
__device__ float g_erow[8u*96*96*96];   // [n,h,w,v]
__device__ float g_ecol[8u*96*96*96];   // [n,w,h,j]

// ---------------- generic batched SGEMM with bias ----------------
// Y[n, m, p] = sum_k A[m,k] * B[n, k, p] + bias[m]
template<int BM, int BN, int BK, int TM, int TN>
__global__ __launch_bounds__((BM/TM)*(BN/TN))
void sgemm_bias(const float* __restrict__ A, const float* __restrict__ bias,
                const float* __restrict__ B, float* __restrict__ Cd,
                int K, int P, long sB, long sC)
{
    constexpr int THREADS = (BM/TM)*(BN/TN);
    __shared__ float As[BK][BM];
    __shared__ float Bs[BK][BN];
    const int tid = threadIdx.x;
    const float* Bn = B + (long)blockIdx.z * sB;
    float* Cn = Cd + (long)blockIdx.z * sC;
    const int bm = blockIdx.y * BM, bn = blockIdx.x * BN;
    const int tx = tid % (BN/TN), ty = tid / (BN/TN);

    float acc[TM][TN];
#pragma unroll
    for (int i = 0; i < TM; i++)
#pragma unroll
        for (int j = 0; j < TN; j++) acc[i][j] = 0.f;

    for (int k0 = 0; k0 < K; k0 += BK) {
#pragma unroll
        for (int i = tid; i < BM*BK; i += THREADS) {
            int r = i / BK, c = i % BK;
            As[c][r] = A[(long)(bm + r) * K + k0 + c];
        }
#pragma unroll
        for (int i = tid; i < BK*BN; i += THREADS) {
            int r = i / BN, c = i % BN;
            Bs[r][c] = Bn[(long)(k0 + r) * P + bn + c];
        }
        __syncthreads();
#pragma unroll
        for (int kk = 0; kk < BK; kk++) {
            float a[TM], b[TN];
#pragma unroll
            for (int i = 0; i < TM; i += 4)
                *(float4*)(a + i) = *(const float4*)&As[kk][ty*TM + i];
#pragma unroll
            for (int j = 0; j < TN; j += 4)
                *(float4*)(b + j) = *(const float4*)&Bs[kk][tx*TN + j];
#pragma unroll
            for (int i = 0; i < TM; i++)
#pragma unroll
                for (int j = 0; j < TN; j++)
                    acc[i][j] = fmaf(a[i], b[j], acc[i][j]);
        }
        __syncthreads();
    }
#pragma unroll
    for (int i = 0; i < TM; i++) {
        float bi = bias[bm + ty*TM + i];
#pragma unroll
        for (int j = 0; j < TN; j++)
            Cn[(long)(bm + ty*TM + i) * P + bn + tx*TN + j] = acc[i][j] + bi;
    }
}

// ---------------- transpose last two 96x96 dims ----------------
__global__ __launch_bounds__(256)
void transpose96(const float* __restrict__ in, float* __restrict__ out)
{
    __shared__ float t[32][33];
    const long base = (long)blockIdx.z * 9216;
    const int h0 = blockIdx.y * 32, w0 = blockIdx.x * 32;
    const int tx = threadIdx.x, ty0 = threadIdx.y;
#pragma unroll
    for (int i = ty0; i < 32; i += 8)
        t[i][tx] = in[base + (long)(h0 + i) * 96 + w0 + tx];
    __syncthreads();
#pragma unroll
    for (int i = ty0; i < 32; i += 8)
        out[base + (long)(w0 + i) * 96 + h0 + tx] = t[tx][i];
}

// ---------------- energies: e[a][b] = sum_c q[c][a]*k[c][b] per (n,r) ----------------
// row:  r=h, a=w, b=v, inputs q,k  [n,c,h,w]     -> g_erow[n,h,w,v]
// col:  r=w, a=h, b=j, inputs qT,kT [n,c,w,h]    -> g_ecol[n,w,h,j]  (diag a==b masked)
template<bool MASK>
__global__ __launch_bounds__(256)
void energy_kernel(const float* __restrict__ q, const float* __restrict__ k,
                   float* __restrict__ e)
{
    __shared__ float qs[64][96];
    __shared__ float ks[64][96];
    const int n = blockIdx.y, r = blockIdx.x;
    const int tid = threadIdx.x;
    const long qb = (long)n * 64 * 9216 + (long)r * 96;
#pragma unroll
    for (int i = tid; i < 64*96; i += 256) {
        int c = i / 96, p = i % 96;
        qs[c][p] = q[qb + (long)c * 9216 + p];
        ks[c][p] = k[qb + (long)c * 9216 + p];
    }
    __syncthreads();
    const int tx = tid % 16, ty = tid / 16;
    float acc[6][6];
#pragma unroll
    for (int i = 0; i < 6; i++)
#pragma unroll
        for (int j = 0; j < 6; j++) acc[i][j] = 0.f;
#pragma unroll 8
    for (int cc = 0; cc < 64; cc++) {
        float a[6], b[6];
#pragma unroll
        for (int i = 0; i < 6; i++) a[i] = qs[cc][ty*6 + i];
#pragma unroll
        for (int j = 0; j < 6; j++) b[j] = ks[cc][tx*6 + j];
#pragma unroll
        for (int i = 0; i < 6; i++)
#pragma unroll
            for (int j = 0; j < 6; j++)
                acc[i][j] = fmaf(a[i], b[j], acc[i][j]);
    }
    const long eb = (long)(n*96 + r) * 96 * 96;
#pragma unroll
    for (int i = 0; i < 6; i++) {
        int aa = ty*6 + i;
#pragma unroll
        for (int j = 0; j < 6; j++) {
            int bb = tx*6 + j;
            float vv = acc[i][j];
            if (MASK && aa == bb) vv = NEGV;
            e[eb + (long)aa * 96 + bb] = vv;
        }
    }
}

// ---------------- softmax over concat(row 96, col 96) per pixel ----------------
__global__ __launch_bounds__(256)
void softmax_kernel(float* __restrict__ arow, float* __restrict__ acol)
{
    const int gtid = blockIdx.x * 256 + threadIdx.x;
    const int pix = gtid >> 5;
    const int lane = threadIdx.x & 31;
    const int n = pix / 9216, rem = pix % 9216;
    const int h = rem / 96, w = rem % 96;
    float* pr = arow + ((long)(n*96 + h) * 96 + w) * 96;
    float* pc = acol + ((long)(n*96 + w) * 96 + h) * 96;
    float v[6];
#pragma unroll
    for (int t = 0; t < 3; t++) {
        v[t]     = pr[lane + 32*t];
        v[3 + t] = pc[lane + 32*t];
    }
    float m = v[0];
#pragma unroll
    for (int t = 1; t < 6; t++) m = fmaxf(m, v[t]);
#pragma unroll
    for (int o = 16; o; o >>= 1) m = fmaxf(m, __shfl_xor_sync(0xffffffffu, m, o));
    float s = 0.f;
#pragma unroll
    for (int t = 0; t < 6; t++) { v[t] = __expf(v[t] - m); s += v[t]; }
#pragma unroll
    for (int o = 16; o; o >>= 1) s += __shfl_xor_sync(0xffffffffu, s, o);
    const float inv = 1.0f / s;
#pragma unroll
    for (int t = 0; t < 3; t++) {
        pr[lane + 32*t] = v[t] * inv;
        pc[lane + 32*t] = v[3 + t] * inv;
    }
}

// ---------------- aggregation: dst[n,c,r,a] = sum_b attn[n,r,a,b]*vsrc[n,c,r,b] ---
// row:  attn=g_erow (normalized), vsrc=g_v,  dst=d_out  (r=h,a=w,b=v)
// col:  attn=g_ecol (normalized), vsrc=g_vT, dst=g_colT (r=w,a=h,b=j)
__global__ __launch_bounds__(256)
void agg_kernel(const float* __restrict__ attn, const float* __restrict__ vsrc,
                float* __restrict__ dst)
{
    __shared__ float Vs[128][49];
    __shared__ float Asl[96][49];
    const int n = blockIdx.z, r = blockIdx.y, c0 = blockIdx.x * 128;
    const int tid = threadIdx.x;
    const long ab = (long)(n*96 + r) * 96 * 96;
    const long vb = ((long)n * 512 + c0) * 9216 + (long)r * 96;
    const int tx = tid % 16, ty = tid / 16;
    float acc[8][6];
#pragma unroll
    for (int i = 0; i < 8; i++)
#pragma unroll
        for (int j = 0; j < 6; j++) acc[i][j] = 0.f;

    for (int b0 = 0; b0 < 96; b0 += 48) {
#pragma unroll
        for (int i = tid; i < 96*48; i += 256) {
            int a = i / 48, b = i % 48;
            Asl[a][b] = attn[ab + (long)a * 96 + b0 + b];
        }
#pragma unroll
        for (int i = tid; i < 128*48; i += 256) {
            int c = i / 48, b = i % 48;
            Vs[c][b] = vsrc[vb + (long)c * 9216 + b0 + b];
        }
        __syncthreads();
#pragma unroll 8
        for (int bb = 0; bb < 48; bb++) {
            float av[8], aa[6];
#pragma unroll
            for (int i = 0; i < 8; i++) av[i] = Vs[ty*8 + i][bb];
#pragma unroll
            for (int j = 0; j < 6; j++) aa[j] = Asl[tx*6 + j][bb];
#pragma unroll
            for (int i = 0; i < 8; i++)
#pragma unroll
                for (int j = 0; j < 6; j++)
                    acc[i][j] = fmaf(av[i], aa[j], acc[i][j]);
        }
        __syncthreads();
    }
#pragma unroll
    for (int i = 0; i < 8; i++) {
        long o = ((long)n * 512 + c0 + ty*8 + i) * 9216 + (long)r * 96 + tx*6;
#pragma unroll
        for (int j = 0; j < 6; j++) dst[o + j] = acc[i][j];
    }
}

// ---------------- finalize: out = gamma*(rowpart(out) + colT^T) + x ----------------
__global__ __launch_bounds__(256)
void finalize_kernel(const float* __restrict__ colT, const float* __restrict__ x,
                     const float* __restrict__ gamma, float* __restrict__ out)
{
    __shared__ float t[32][33];
    const long base = (long)blockIdx.z * 9216;
    const int h0 = blockIdx.y * 32, w0 = blockIdx.x * 32;
    const int tx = threadIdx.x, ty0 = threadIdx.y;
#pragma unroll
    for (int i = ty0; i < 32; i += 8)
        t[i][tx] = colT[base + (long)(w0 + i) * 96 + h0 + tx];
    __syncthreads();
    const float g = gamma[0];
#pragma unroll
    for (int i = ty0; i < 32; i += 8) {
        long idx = base + (long)(h0 + i) * 96 + w0 + tx;
        out[idx] = g * (out[idx] + t[tx][i]) + x[idx];
    }
}

// ---------------- launch ----------------
extern "C" void kernel_launch(void* const* d_in, const int* in_sizes, int n_in,
                              void* d_out, int out_size)
{
    (void)in_sizes; (void)n_in; (void)out_size;
    const float* x     = (const float*)d_in[0];
    const float* wq    = (const float*)d_in[1];
    const float* bq    = (const float*)d_in[2];
    const float* wk    = (const float*)d_in[3];
    const float* bk    = (const float*)d_in[4];
    const float* wv    = (const float*)d_in[5];
    const float* bv    = (const float*)d_in[6];
    const float* gamma = (const float*)d_in[7];
    float* out = (float*)d_out;

    float *q, *k, *qT, *kT, *v, *vT, *colT, *erow, *ecol;
    cudaGetSymbolAddress((void**)&q,    g_q);
    cudaGetSymbolAddress((void**)&k,    g_k);
    cudaGetSymbolAddress((void**)&qT,   g_qT);
    cudaGetSymbolAddress((void**)&kT,   g_kT);
    cudaGetSymbolAddress((void**)&v,    g_v);
    cudaGetSymbolAddress((void**)&vT,   g_vT);
    cudaGetSymbolAddress((void**)&colT, g_colT);
    cudaGetSymbolAddress((void**)&erow, g_erow);
    cudaGetSymbolAddress((void**)&ecol, g_ecol);

    const long sX = (long)512 * 9216;   // x batch stride
    const long sQ = (long)64  * 9216;   // q/k batch stride

    // 1) projections
    sgemm_bias<64,128,16,4,8><<<dim3(72,1,8), 256>>>(wq, bq, x, q, 512, 9216, sX, sQ);
    sgemm_bias<64,128,16,4,8><<<dim3(72,1,8), 256>>>(wk, bk, x, k, 512, 9216, sX, sQ);
    sgemm_bias<128,128,16,8,8><<<dim3(72,4,8), 256>>>(wv, bv, x, v, 512, 9216, sX, sX);

    // 2) transposes (column-direction contiguity)
    transpose96<<<dim3(3,3,8*64),  dim3(32,8)>>>(q, qT);
    transpose96<<<dim3(3,3,8*64),  dim3(32,8)>>>(k, kT);
    transpose96<<<dim3(3,3,8*512), dim3(32,8)>>>(v, vT);

    // 3) energies
    energy_kernel<false><<<dim3(96,8), 256>>>(q,  k,  erow);
    energy_kernel<true ><<<dim3(96,8), 256>>>(qT, kT, ecol);

    // 4) softmax over 192 (row||col) per pixel — in place
    softmax_kernel<<<9216, 256>>>(erow, ecol);

    // 5) aggregation
    agg_kernel<<<dim3(4,96,8), 256>>>(erow, v,  out);    // row part -> d_out
    agg_kernel<<<dim3(4,96,8), 256>>>(ecol, vT, colT);   // col part -> colT

    // 6) finalize: out = gamma*(row + col) + x
    finalize_kernel<<<dim3(3,3,8*512), dim3(32,8)>>>(colT, x, gamma, out);
}

// round 3
// speedup vs baseline: 2.1390x; 2.1390x over previous
#include <cuda_runtime.h>
#include <cstdint>

#define NEGV (-1e30f)

// Problem constants: N=8, C=512, Cq=64, H=W=96
// x: [8,512,96,96] fp32

// ---------------- scratch (device globals; allocation-free) ----------------
__device__ float g_q   [8u*64*9216];    // [n,cq,h,w]
__device__ float g_k   [8u*64*9216];
__device__ float g_qT  [8u*64*9216];    // [n,cq,w,h]
__device__ float g_kT  [8u*64*9216];
__device__ float g_v   [8u*512*9216];   // [n,c,h,w]
__device__ float g_vT  [8u*512*9216];   // [n,c,w,h]
__device__ float g_colT[8u*512*9216];   // [n,c,w,h]
__device__ float g_erow[8u*96*96*96];   // [n,h,w,v]
__device__ float g_ecol[8u*96*96*96];   // [n,w,h,j]
__device__ float g_wpack[640*512];      // [wq;wk;wv]
__device__ float g_bpack[640];

// ---------------- helpers ----------------
__device__ __forceinline__ uint32_t f2tf32(float f) {
    uint32_t u;
    asm("cvt.rna.tf32.f32 %0, %1;" : "=r"(u) : "f"(f));
    return u;
}

__device__ __forceinline__ void mma_tf32(float c[4], uint32_t a0, uint32_t a1,
                                         uint32_t a2, uint32_t a3,
                                         uint32_t b0, uint32_t b1) {
    asm volatile(
        "mma.sync.aligned.m16n8k8.row.col.f32.tf32.tf32.f32 "
        "{%0,%1,%2,%3}, {%4,%5,%6,%7}, {%8,%9}, {%0,%1,%2,%3};"
        : "+f"(c[0]), "+f"(c[1]), "+f"(c[2]), "+f"(c[3])
        : "r"(a0), "r"(a1), "r"(a2), "r"(a3), "r"(b0), "r"(b1));
}

// ---------------- weight packing ----------------
__global__ __launch_bounds__(256)
void pack_w(const float* __restrict__ wq, const float* __restrict__ wk,
            const float* __restrict__ wv, const float* __restrict__ bq,
            const float* __restrict__ bk, const float* __restrict__ bv,
            float* __restrict__ W, float* __restrict__ B)
{
    int idx = blockIdx.x * 256 + threadIdx.x;
    if (idx < 640 * 512) {
        int r = idx >> 9, c = idx & 511;
        float val = (r < 64) ? wq[r * 512 + c]
                  : (r < 128) ? wk[(r - 64) * 512 + c]
                              : wv[(r - 128) * 512 + c];
        W[idx] = val;
    }
    if (idx < 640)
        B[idx] = (idx < 64) ? bq[idx] : (idx < 128) ? bk[idx - 64] : bv[idx - 128];
}

// ---------------- fused QKV projection (tf32 MMA) ----------------
// Y[n, m, p] = sum_k W[m,k]*X[n,k,p] + bias[m];  m<64 -> q, <128 -> k, else v
__global__ __launch_bounds__(256, 1)
void qkv_mma(const float* __restrict__ W, const float* __restrict__ bias,
             const float* __restrict__ X,
             float* __restrict__ q, float* __restrict__ k, float* __restrict__ v)
{
    __shared__ uint32_t As[128][20];   // [m][k], stride 20 -> conflict-free frag loads
    __shared__ uint32_t Bs[128][20];   // [n][k]
    const int n = blockIdx.z;
    const int bm = blockIdx.y * 128, bn = blockIdx.x * 128;
    const int tid = threadIdx.x;
    const int warp = tid >> 5, lane = tid & 31;
    const int gid = lane >> 2, tig = lane & 3;
    const int wm = (warp >> 2) * 64;     // 2 warps along M
    const int wn = (warp & 3) * 32;      // 4 warps along N
    const float* Xn = X + (long)n * 512 * 9216;

    float acc[4][4][4];
#pragma unroll
    for (int mt = 0; mt < 4; mt++)
#pragma unroll
        for (int nt = 0; nt < 4; nt++)
#pragma unroll
            for (int i = 0; i < 4; i++) acc[mt][nt][i] = 0.f;

    for (int k0 = 0; k0 < 512; k0 += 16) {
        // W tile: 128 x 16
        {
            int r = tid >> 1, hf = (tid & 1) * 8;
            const float4* p = (const float4*)&W[(long)(bm + r) * 512 + k0 + hf];
            float4 f0 = p[0], f1 = p[1];
            As[r][hf + 0] = f2tf32(f0.x); As[r][hf + 1] = f2tf32(f0.y);
            As[r][hf + 2] = f2tf32(f0.z); As[r][hf + 3] = f2tf32(f0.w);
            As[r][hf + 4] = f2tf32(f1.x); As[r][hf + 5] = f2tf32(f1.y);
            As[r][hf + 6] = f2tf32(f1.z); As[r][hf + 7] = f2tf32(f1.w);
        }
        // X tile: 16 x 128, stored transposed Bs[n][k]
        {
            int r = tid >> 4, c = (tid & 15) * 8;
            const float4* p = (const float4*)&Xn[(long)(k0 + r) * 9216 + bn + c];
            float4 f0 = p[0], f1 = p[1];
            Bs[c + 0][r] = f2tf32(f0.x); Bs[c + 1][r] = f2tf32(f0.y);
            Bs[c + 2][r] = f2tf32(f0.z); Bs[c + 3][r] = f2tf32(f0.w);
            Bs[c + 4][r] = f2tf32(f1.x); Bs[c + 5][r] = f2tf32(f1.y);
            Bs[c + 6][r] = f2tf32(f1.z); Bs[c + 7][r] = f2tf32(f1.w);
        }
        __syncthreads();
#pragma unroll
        for (int ks = 0; ks < 2; ks++) {
            const int kb = ks * 8;
            uint32_t af[4][4], bf[4][2];
#pragma unroll
            for (int mt = 0; mt < 4; mt++) {
                int rb = wm + mt * 16;
                af[mt][0] = As[rb + gid    ][kb + tig];
                af[mt][1] = As[rb + gid + 8][kb + tig];
                af[mt][2] = As[rb + gid    ][kb + tig + 4];
                af[mt][3] = As[rb + gid + 8][kb + tig + 4];
            }
#pragma unroll
            for (int nt = 0; nt < 4; nt++) {
                int nb = wn + nt * 8;
                bf[nt][0] = Bs[nb + gid][kb + tig];
                bf[nt][1] = Bs[nb + gid][kb + tig + 4];
            }
#pragma unroll
            for (int mt = 0; mt < 4; mt++)
#pragma unroll
                for (int nt = 0; nt < 4; nt++)
                    mma_tf32(acc[mt][nt], af[mt][0], af[mt][1], af[mt][2], af[mt][3],
                             bf[nt][0], bf[nt][1]);
        }
        __syncthreads();
    }

    // epilogue
#pragma unroll
    for (int mt = 0; mt < 4; mt++) {
#pragma unroll
        for (int half = 0; half < 2; half++) {
            int row = bm + wm + mt * 16 + gid + half * 8;
            float bi = bias[row];
            float* dst;
            if (row < 64)        dst = q + ((long)n * 64  + row)       * 9216;
            else if (row < 128)  dst = k + ((long)n * 64  + row - 64)  * 9216;
            else                 dst = v + ((long)n * 512 + row - 128) * 9216;
#pragma unroll
            for (int nt = 0; nt < 4; nt++) {
                int col = bn + wn + nt * 8 + 2 * tig;
                float2 val;
                val.x = acc[mt][nt][half * 2 + 0] + bi;
                val.y = acc[mt][nt][half * 2 + 1] + bi;
                *(float2*)&dst[col] = val;
            }
        }
    }
}

// ---------------- transpose last two 96x96 dims ----------------
__global__ __launch_bounds__(256)
void transpose96(const float* __restrict__ in, float* __restrict__ out)
{
    __shared__ float t[32][33];
    const long base = (long)blockIdx.z * 9216;
    const int h0 = blockIdx.y * 32, w0 = blockIdx.x * 32;
    const int tx = threadIdx.x, ty0 = threadIdx.y;
#pragma unroll
    for (int i = ty0; i < 32; i += 8)
        t[i][tx] = in[base + (long)(h0 + i) * 96 + w0 + tx];
    __syncthreads();
#pragma unroll
    for (int i = ty0; i < 32; i += 8)
        out[base + (long)(w0 + i) * 96 + h0 + tx] = t[tx][i];
}

// ---------------- energies: e[a][b] = sum_c q[c][a]*k[c][b] per (n,r) -------
template<bool MASK>
__global__ __launch_bounds__(256)
void energy_kernel(const float* __restrict__ q, const float* __restrict__ k,
                   float* __restrict__ e)
{
    __shared__ float qs[64][96];
    __shared__ float ks[64][96];
    const int n = blockIdx.y, r = blockIdx.x;
    const int tid = threadIdx.x;
    const long qb = (long)n * 64 * 9216 + (long)r * 96;
#pragma unroll
    for (int i = tid; i < 64*96; i += 256) {
        int c = i / 96, p = i % 96;
        qs[c][p] = q[qb + (long)c * 9216 + p];
        ks[c][p] = k[qb + (long)c * 9216 + p];
    }
    __syncthreads();
    const int tx = tid % 16, ty = tid / 16;
    float acc[6][6];
#pragma unroll
    for (int i = 0; i < 6; i++)
#pragma unroll
        for (int j = 0; j < 6; j++) acc[i][j] = 0.f;
#pragma unroll 8
    for (int cc = 0; cc < 64; cc++) {
        float a[6], b[6];
#pragma unroll
        for (int i = 0; i < 6; i++) a[i] = qs[cc][ty*6 + i];
#pragma unroll
        for (int j = 0; j < 6; j++) b[j] = ks[cc][tx*6 + j];
#pragma unroll
        for (int i = 0; i < 6; i++)
#pragma unroll
            for (int j = 0; j < 6; j++)
                acc[i][j] = fmaf(a[i], b[j], acc[i][j]);
    }
    const long eb = (long)(n*96 + r) * 96 * 96;
#pragma unroll
    for (int i = 0; i < 6; i++) {
        int aa = ty*6 + i;
#pragma unroll
        for (int j = 0; j < 6; j++) {
            int bb = tx*6 + j;
            float vv = acc[i][j];
            if (MASK && aa == bb) vv = NEGV;
            e[eb + (long)aa * 96 + bb] = vv;
        }
    }
}

// ---------------- softmax over concat(row 96, col 96) per pixel -------------
__global__ __launch_bounds__(256)
void softmax_kernel(float* __restrict__ arow, float* __restrict__ acol)
{
    const int gtid = blockIdx.x * 256 + threadIdx.x;
    const int pix = gtid >> 5;
    const int lane = threadIdx.x & 31;
    const int n = pix / 9216, rem = pix % 9216;
    const int h = rem / 96, w = rem % 96;
    float* pr = arow + ((long)(n*96 + h) * 96 + w) * 96;
    float* pc = acol + ((long)(n*96 + w) * 96 + h) * 96;
    float v[6];
#pragma unroll
    for (int t = 0; t < 3; t++) {
        v[t]     = pr[lane + 32*t];
        v[3 + t] = pc[lane + 32*t];
    }
    float m = v[0];
#pragma unroll
    for (int t = 1; t < 6; t++) m = fmaxf(m, v[t]);
#pragma unroll
    for (int o = 16; o; o >>= 1) m = fmaxf(m, __shfl_xor_sync(0xffffffffu, m, o));
    float s = 0.f;
#pragma unroll
    for (int t = 0; t < 6; t++) { v[t] = __expf(v[t] - m); s += v[t]; }
#pragma unroll
    for (int o = 16; o; o >>= 1) s += __shfl_xor_sync(0xffffffffu, s, o);
    const float inv = 1.0f / s;
#pragma unroll
    for (int t = 0; t < 3; t++) {
        pr[lane + 32*t] = v[t] * inv;
        pc[lane + 32*t] = v[3 + t] * inv;
    }
}

// ---------------- aggregation (tf32 MMA) ------------------------------------
// dst[n,c,r,a] = sum_b attn[n,r,a,b] * vsrc[n,c,r,b]
// GEMM per (n,r): M=512 (c), N=96 (a), K=96 (b); K split in two 48-tiles.
__global__ __launch_bounds__(256, 1)
void agg_mma(const float* __restrict__ attn, const float* __restrict__ vsrc,
             float* __restrict__ dst)
{
    __shared__ uint32_t Vs[128][52];     // [c][b]
    __shared__ uint32_t Atts[96][52];    // [a][b]
    const int n = blockIdx.z, rr = blockIdx.y, c0 = blockIdx.x * 128;
    const int tid = threadIdx.x;
    const int warp = tid >> 5, lane = tid & 31;
    const int gid = lane >> 2, tig = lane & 3;
    const int wm = (warp >> 1) * 32;   // 4 warps along M (32 each)
    const int wn = (warp & 1) * 48;    // 2 warps along N (48 each)
    const long ab = (long)(n*96 + rr) * 96 * 96;
    const long vb = ((long)n * 512 + c0) * 9216 + (long)rr * 96;

    float acc[2][6][4];
#pragma unroll
    for (int mt = 0; mt < 2; mt++)
#pragma unroll
        for (int nt = 0; nt < 6; nt++)
#pragma unroll
            for (int i = 0; i < 4; i++) acc[mt][nt][i] = 0.f;

    for (int b0 = 0; b0 < 96; b0 += 48) {
        // V tile 128 x 48 (float4 loads)
#pragma unroll
        for (int i = tid; i < 128 * 12; i += 256) {
            int r = i / 12, cp = (i % 12) * 4;
            float4 f = *(const float4*)&vsrc[vb + (long)r * 9216 + b0 + cp];
            Vs[r][cp + 0] = f2tf32(f.x); Vs[r][cp + 1] = f2tf32(f.y);
            Vs[r][cp + 2] = f2tf32(f.z); Vs[r][cp + 3] = f2tf32(f.w);
        }
        // Att tile 96 x 48
#pragma unroll
        for (int i = tid; i < 96 * 12; i += 256) {
            int a = i / 12, cp = (i % 12) * 4;
            float4 f = *(const float4*)&attn[ab + (long)a * 96 + b0 + cp];
            Atts[a][cp + 0] = f2tf32(f.x); Atts[a][cp + 1] = f2tf32(f.y);
            Atts[a][cp + 2] = f2tf32(f.z); Atts[a][cp + 3] = f2tf32(f.w);
        }
        __syncthreads();
#pragma unroll
        for (int ks = 0; ks < 6; ks++) {
            const int kb = ks * 8;
            uint32_t af[2][4], bf[6][2];
#pragma unroll
            for (int mt = 0; mt < 2; mt++) {
                int rb = wm + mt * 16;
                af[mt][0] = Vs[rb + gid    ][kb + tig];
                af[mt][1] = Vs[rb + gid + 8][kb + tig];
                af[mt][2] = Vs[rb + gid    ][kb + tig + 4];
                af[mt][3] = Vs[rb + gid + 8][kb + tig + 4];
            }
#pragma unroll
            for (int nt = 0; nt < 6; nt++) {
                int nb = wn + nt * 8;
                bf[nt][0] = Atts[nb + gid][kb + tig];
                bf[nt][1] = Atts[nb + gid][kb + tig + 4];
            }
#pragma unroll
            for (int mt = 0; mt < 2; mt++)
#pragma unroll
                for (int nt = 0; nt < 6; nt++)
                    mma_tf32(acc[mt][nt], af[mt][0], af[mt][1], af[mt][2], af[mt][3],
                             bf[nt][0], bf[nt][1]);
        }
        __syncthreads();
    }

    // epilogue: dst[((n*512+c)*96 + rr)*96 + a]
#pragma unroll
    for (int mt = 0; mt < 2; mt++) {
#pragma unroll
        for (int half = 0; half < 2; half++) {
            int c = c0 + wm + mt * 16 + gid + half * 8;
            float* drow = dst + (((long)n * 512 + c) * 96 + rr) * 96;
#pragma unroll
            for (int nt = 0; nt < 6; nt++) {
                int a = wn + nt * 8 + 2 * tig;
                float2 val;
                val.x = acc[mt][nt][half * 2 + 0];
                val.y = acc[mt][nt][half * 2 + 1];
                *(float2*)&drow[a] = val;
            }
        }
    }
}

// ---------------- finalize: out = gamma*(rowpart(out) + colT^T) + x ---------
__global__ __launch_bounds__(256)
void finalize_kernel(const float* __restrict__ colT, const float* __restrict__ x,
                     const float* __restrict__ gamma, float* __restrict__ out)
{
    __shared__ float t[32][33];
    const long base = (long)blockIdx.z * 9216;
    const int h0 = blockIdx.y * 32, w0 = blockIdx.x * 32;
    const int tx = threadIdx.x, ty0 = threadIdx.y;
#pragma unroll
    for (int i = ty0; i < 32; i += 8)
        t[i][tx] = colT[base + (long)(w0 + i) * 96 + h0 + tx];
    __syncthreads();
    const float g = gamma[0];
#pragma unroll
    for (int i = ty0; i < 32; i += 8) {
        long idx = base + (long)(h0 + i) * 96 + w0 + tx;
        out[idx] = g * (out[idx] + t[tx][i]) + x[idx];
    }
}

// ---------------- launch ----------------
extern "C" void kernel_launch(void* const* d_in, const int* in_sizes, int n_in,
                              void* d_out, int out_size)
{
    (void)in_sizes; (void)n_in; (void)out_size;
    const float* x     = (const float*)d_in[0];
    const float* wq    = (const float*)d_in[1];
    const float* bq    = (const float*)d_in[2];
    const float* wk    = (const float*)d_in[3];
    const float* bk    = (const float*)d_in[4];
    const float* wv    = (const float*)d_in[5];
    const float* bv    = (const float*)d_in[6];
    const float* gamma = (const float*)d_in[7];
    float* out = (float*)d_out;

    float *q, *k, *qT, *kT, *v, *vT, *colT, *erow, *ecol, *W, *B;
    cudaGetSymbolAddress((void**)&q,    g_q);
    cudaGetSymbolAddress((void**)&k,    g_k);
    cudaGetSymbolAddress((void**)&qT,   g_qT);
    cudaGetSymbolAddress((void**)&kT,   g_kT);
    cudaGetSymbolAddress((void**)&v,    g_v);
    cudaGetSymbolAddress((void**)&vT,   g_vT);
    cudaGetSymbolAddress((void**)&colT, g_colT);
    cudaGetSymbolAddress((void**)&erow, g_erow);
    cudaGetSymbolAddress((void**)&ecol, g_ecol);
    cudaGetSymbolAddress((void**)&W,    g_wpack);
    cudaGetSymbolAddress((void**)&B,    g_bpack);

    // 0) pack weights [wq;wk;wv] -> 640x512
    pack_w<<<1280, 256>>>(wq, wk, wv, bq, bk, bv, W, B);

    // 1) fused QKV projection (tf32 MMA)
    qkv_mma<<<dim3(72, 5, 8), 256>>>(W, B, x, q, k, v);

    // 2) transposes (column-direction contiguity)
    transpose96<<<dim3(3,3,8*64),  dim3(32,8)>>>(q, qT);
    transpose96<<<dim3(3,3,8*64),  dim3(32,8)>>>(k, kT);
    transpose96<<<dim3(3,3,8*512), dim3(32,8)>>>(v, vT);

    // 3) energies
    energy_kernel<false><<<dim3(96,8), 256>>>(q,  k,  erow);
    energy_kernel<true ><<<dim3(96,8), 256>>>(qT, kT, ecol);

    // 4) softmax over 192 (row||col) per pixel — in place
    softmax_kernel<<<9216, 256>>>(erow, ecol);

    // 5) aggregation (tf32 MMA)
    agg_mma<<<dim3(4,96,8), 256>>>(erow, v,  out);    // row part -> d_out
    agg_mma<<<dim3(4,96,8), 256>>>(ecol, vT, colT);   // col part -> colT

    // 6) finalize: out = gamma*(row + col) + x
    finalize_kernel<<<dim3(3,3,8*512), dim3(32,8)>>>(colT, x, gamma, out);
}

// round 9
// speedup vs baseline: 3.5044x; 1.6383x over previous
#include <cuda_runtime.h>
#include <cuda_bf16.h>
#include <cstdint>

#define NEGV (-1e30f)

// Problem constants: N=8, C=512, Cq=64, H=W=96

// ---------------- scratch (device globals; allocation-free) ----------------
__device__ float g_q   [8u*64*9216];          // [n,cq,h,w]
__device__ float g_k   [8u*64*9216];
__device__ float g_qT  [8u*64*9216];          // [n,cq,w,h]
__device__ float g_kT  [8u*64*9216];
__device__ float g_colT[8u*512*9216];         // [n,c,w,h] col-attn out (f32)
__device__ float g_erow[8u*96*96*96];         // [n,h,w,v]
__device__ float g_ecol[8u*96*96*96];         // [n,w,h,j]
__device__ float g_bpack[640];
__device__ __nv_bfloat16 g_wbf [640*512];     // packed [wq;wk;wv] bf16
__device__ __nv_bfloat16 g_xT  [8u*9216*512]; // x transposed [n,p,c] bf16
__device__ __nv_bfloat16 g_vbf [8u*512*9216]; // v [n,c,h,w] bf16
__device__ __nv_bfloat16 g_vTbf[8u*512*9216]; // v [n,c,w,h] bf16

// ---------------- helpers ----------------
__device__ __forceinline__ void mma_bf16(float c[4], uint32_t a0, uint32_t a1,
                                         uint32_t a2, uint32_t a3,
                                         uint32_t b0, uint32_t b1) {
    asm volatile(
        "mma.sync.aligned.m16n8k16.row.col.f32.bf16.bf16.f32 "
        "{%0,%1,%2,%3}, {%4,%5,%6,%7}, {%8,%9}, {%0,%1,%2,%3};"
        : "+f"(c[0]), "+f"(c[1]), "+f"(c[2]), "+f"(c[3])
        : "r"(a0), "r"(a1), "r"(a2), "r"(a3), "r"(b0), "r"(b1));
}

__device__ __forceinline__ uint32_t pack_bf2(float lo, float hi) {
    __nv_bfloat162 h = __floats2bfloat162_rn(lo, hi);   // h.x = lo
    return *(uint32_t*)&h;
}

__device__ __forceinline__ void cp_async16(uint32_t saddr, const void* gptr) {
    asm volatile("cp.async.cg.shared.global [%0], [%1], 16;" :: "r"(saddr), "l"(gptr));
}
__device__ __forceinline__ void cp_commit() { asm volatile("cp.async.commit_group;"); }
template<int N>
__device__ __forceinline__ void cp_wait() { asm volatile("cp.async.wait_group %0;" :: "n"(N)); }

// ---------------- weight packing (f32 -> bf16) ----------------
__global__ __launch_bounds__(256)
void pack_w(const float* __restrict__ wq, const float* __restrict__ wk,
            const float* __restrict__ wv, const float* __restrict__ bq,
            const float* __restrict__ bk, const float* __restrict__ bv,
            __nv_bfloat16* __restrict__ W, float* __restrict__ B)
{
    int idx = blockIdx.x * 256 + threadIdx.x;
    if (idx < 640 * 512) {
        int r = idx >> 9, c = idx & 511;
        float val = (r < 64) ? wq[r * 512 + c]
                  : (r < 128) ? wk[(r - 64) * 512 + c]
                              : wv[(r - 128) * 512 + c];
        W[idx] = __float2bfloat16(val);
    }
    if (idx < 640)
        B[idx] = (idx < 64) ? bq[idx] : (idx < 128) ? bk[idx - 64] : bv[idx - 128];
}

// ---------------- x convert+transpose: x[n,c,p] f32 -> xT[n,p,c] bf16 -------
__global__ __launch_bounds__(256)
void xcvt_kernel(const float* __restrict__ x, __nv_bfloat16* __restrict__ xT)
{
    __shared__ float t[32][33];
    const int n = blockIdx.z;
    const int c0 = blockIdx.y * 32, p0 = blockIdx.x * 32;
    const int tx = threadIdx.x, ty0 = threadIdx.y;
    const float* xn = x + (long)n * 512 * 9216;
#pragma unroll
    for (int i = ty0; i < 32; i += 8)
        t[i][tx] = xn[(long)(c0 + i) * 9216 + p0 + tx];
    __syncthreads();
    __nv_bfloat16* xTn = xT + (long)n * 9216 * 512;
#pragma unroll
    for (int i = ty0; i < 32; i += 8)
        xTn[(long)(p0 + i) * 512 + c0 + tx] = __float2bfloat16(t[tx][i]);
}

// ---------------- fused QKV projection (bf16 MMA, cp.async double-buffered) -
// Y[n, m, p] = sum_k W[m,k]*x[n,k,p] + bias[m];  m<64 -> q, <128 -> k, else vbf
__global__ __launch_bounds__(256, 1)
void qkv_mma(const __nv_bfloat16* __restrict__ W, const float* __restrict__ bias,
             const __nv_bfloat16* __restrict__ xT,
             float* __restrict__ q, float* __restrict__ k,
             __nv_bfloat16* __restrict__ vbf)
{
    __shared__ uint32_t As[2][128][20];   // [m][kpair] bf16 pairs; pitch 80B (16B-mult)
    __shared__ uint32_t Bs[2][128][20];   // [p][kpair]
    const int n = blockIdx.z;
    const int bm = blockIdx.y * 128, bn = blockIdx.x * 128;
    const int tid = threadIdx.x;
    const int warp = tid >> 5, lane = tid & 31;
    const int gid = lane >> 2, tig = lane & 3;
    const int wm = (warp >> 2) * 64;     // 2 warps along M
    const int wn = (warp & 3) * 32;      // 4 warps along N
    const __nv_bfloat16* xTn = xT + (long)n * 9216 * 512;

    const uint32_t as_base = (uint32_t)__cvta_generic_to_shared(&As[0][0][0]);
    const uint32_t bs_base = (uint32_t)__cvta_generic_to_shared(&Bs[0][0][0]);
    const int r  = tid >> 2, cc = tid & 3;          // chunk 0 mapping
    const int r2 = (tid + 256) >> 2, cc2 = (tid + 256) & 3;

    float acc[4][4][4];
#pragma unroll
    for (int mt = 0; mt < 4; mt++)
#pragma unroll
        for (int nt = 0; nt < 4; nt++)
#pragma unroll
            for (int i = 0; i < 4; i++) acc[mt][nt][i] = 0.f;

    // issue one 32-k tile (A+B) into buffer `buf`
    auto issue = [&](int k0, int buf) {
        cp_async16(as_base + (uint32_t)(((buf*128 + r )*20 + cc *4)*4),
                   &W  [(long)(bm + r ) * 512 + k0 + cc  * 8]);
        cp_async16(bs_base + (uint32_t)(((buf*128 + r )*20 + cc *4)*4),
                   &xTn[(long)(bn + r ) * 512 + k0 + cc  * 8]);
        cp_async16(as_base + (uint32_t)(((buf*128 + r2)*20 + cc2*4)*4),
                   &W  [(long)(bm + r2) * 512 + k0 + cc2 * 8]);
        cp_async16(bs_base + (uint32_t)(((buf*128 + r2)*20 + cc2*4)*4),
                   &xTn[(long)(bn + r2) * 512 + k0 + cc2 * 8]);
        cp_commit();
    };

    issue(0, 0);

    for (int t = 0; t < 16; t++) {
        if (t < 15) { issue((t + 1) * 32, (t + 1) & 1); cp_wait<1>(); }
        else        { cp_wait<0>(); }
        __syncthreads();
        const int buf = t & 1;
#pragma unroll
        for (int ks = 0; ks < 2; ks++) {
            const int kk = ks * 8;
            uint32_t af[4][4], bf[4][2];
#pragma unroll
            for (int mt = 0; mt < 4; mt++) {
                int rb = wm + mt * 16;
                af[mt][0] = As[buf][rb + gid    ][kk + tig];
                af[mt][1] = As[buf][rb + gid + 8][kk + tig];
                af[mt][2] = As[buf][rb + gid    ][kk + tig + 4];
                af[mt][3] = As[buf][rb + gid + 8][kk + tig + 4];
            }
#pragma unroll
            for (int nt = 0; nt < 4; nt++) {
                int nb = wn + nt * 8;
                bf[nt][0] = Bs[buf][nb + gid][kk + tig];
                bf[nt][1] = Bs[buf][nb + gid][kk + tig + 4];
            }
#pragma unroll
            for (int mt = 0; mt < 4; mt++)
#pragma unroll
                for (int nt = 0; nt < 4; nt++)
                    mma_bf16(acc[mt][nt], af[mt][0], af[mt][1], af[mt][2], af[mt][3],
                             bf[nt][0], bf[nt][1]);
        }
        __syncthreads();
    }

    // epilogue
#pragma unroll
    for (int mt = 0; mt < 4; mt++) {
#pragma unroll
        for (int half = 0; half < 2; half++) {
            int row = bm + wm + mt * 16 + gid + half * 8;
            float bi = bias[row];
            if (row < 128) {
                float* dst = (row < 64) ? q + ((long)n * 64 + row) * 9216
                                        : k + ((long)n * 64 + row - 64) * 9216;
#pragma unroll
                for (int nt = 0; nt < 4; nt++) {
                    int col = bn + wn + nt * 8 + 2 * tig;
                    float2 val;
                    val.x = acc[mt][nt][half * 2 + 0] + bi;
                    val.y = acc[mt][nt][half * 2 + 1] + bi;
                    *(float2*)&dst[col] = val;
                }
            } else {
                __nv_bfloat16* dst = vbf + ((long)n * 512 + row - 128) * 9216;
#pragma unroll
                for (int nt = 0; nt < 4; nt++) {
                    int col = bn + wn + nt * 8 + 2 * tig;
                    __nv_bfloat162 hv = __floats2bfloat162_rn(
                        acc[mt][nt][half * 2 + 0] + bi,
                        acc[mt][nt][half * 2 + 1] + bi);
                    *(__nv_bfloat162*)&dst[col] = hv;
                }
            }
        }
    }
}

// ---------------- transpose last two 96x96 dims (f32) ----------------
__global__ __launch_bounds__(256)
void transpose96(const float* __restrict__ in, float* __restrict__ out)
{
    __shared__ float t[32][33];
    const long base = (long)blockIdx.z * 9216;
    const int h0 = blockIdx.y * 32, w0 = blockIdx.x * 32;
    const int tx = threadIdx.x, ty0 = threadIdx.y;
#pragma unroll
    for (int i = ty0; i < 32; i += 8)
        t[i][tx] = in[base + (long)(h0 + i) * 96 + w0 + tx];
    __syncthreads();
#pragma unroll
    for (int i = ty0; i < 32; i += 8)
        out[base + (long)(w0 + i) * 96 + h0 + tx] = t[tx][i];
}

// ---------------- transpose last two 96x96 dims (bf16) ----------------
__global__ __launch_bounds__(256)
void transpose96_bf(const __nv_bfloat16* __restrict__ in, __nv_bfloat16* __restrict__ out)
{
    __shared__ __nv_bfloat16 t[32][33];
    const long base = (long)blockIdx.z * 9216;
    const int h0 = blockIdx.y * 32, w0 = blockIdx.x * 32;
    const int tx = threadIdx.x, ty0 = threadIdx.y;
#pragma unroll
    for (int i = ty0; i < 32; i += 8)
        t[i][tx] = in[base + (long)(h0 + i) * 96 + w0 + tx];
    __syncthreads();
#pragma unroll
    for (int i = ty0; i < 32; i += 8)
        out[base + (long)(w0 + i) * 96 + h0 + tx] = t[tx][i];
}

// ---------------- energies: e[a][b] = sum_c q[c][a]*k[c][b] per (n,r) -------
template<bool MASK>
__global__ __launch_bounds__(256)
void energy_kernel(const float* __restrict__ q, const float* __restrict__ k,
                   float* __restrict__ e)
{
    __shared__ float qs[64][96];
    __shared__ float ks[64][96];
    const int n = blockIdx.y, r = blockIdx.x;
    const int tid = threadIdx.x;
    const long qb = (long)n * 64 * 9216 + (long)r * 96;
#pragma unroll
    for (int i = tid; i < 64*96; i += 256) {
        int c = i / 96, p = i % 96;
        qs[c][p] = q[qb + (long)c * 9216 + p];
        ks[c][p] = k[qb + (long)c * 9216 + p];
    }
    __syncthreads();
    const int tx = tid % 16, ty = tid / 16;
    float acc[6][6];
#pragma unroll
    for (int i = 0; i < 6; i++)
#pragma unroll
        for (int j = 0; j < 6; j++) acc[i][j] = 0.f;
#pragma unroll 8
    for (int cc = 0; cc < 64; cc++) {
        float a[6], b[6];
#pragma unroll
        for (int i = 0; i < 6; i++) a[i] = qs[cc][ty*6 + i];
#pragma unroll
        for (int j = 0; j < 6; j++) b[j] = ks[cc][tx*6 + j];
#pragma unroll
        for (int i = 0; i < 6; i++)
#pragma unroll
            for (int j = 0; j < 6; j++)
                acc[i][j] = fmaf(a[i], b[j], acc[i][j]);
    }
    const long eb = (long)(n*96 + r) * 96 * 96;
#pragma unroll
    for (int i = 0; i < 6; i++) {
        int aa = ty*6 + i;
#pragma unroll
        for (int j = 0; j < 6; j++) {
            int bb = tx*6 + j;
            float vv = acc[i][j];
            if (MASK && aa == bb) vv = NEGV;
            e[eb + (long)aa * 96 + bb] = vv;
        }
    }
}

// ---------------- softmax over concat(row 96, col 96) per pixel -------------
__global__ __launch_bounds__(256)
void softmax_kernel(float* __restrict__ arow, float* __restrict__ acol)
{
    const int gtid = blockIdx.x * 256 + threadIdx.x;
    const int pix = gtid >> 5;
    const int lane = threadIdx.x & 31;
    const int n = pix / 9216, rem = pix % 9216;
    const int h = rem / 96, w = rem % 96;
    float* pr = arow + ((long)(n*96 + h) * 96 + w) * 96;
    float* pc = acol + ((long)(n*96 + w) * 96 + h) * 96;
    float v[6];
#pragma unroll
    for (int t = 0; t < 3; t++) {
        v[t]     = pr[lane + 32*t];
        v[3 + t] = pc[lane + 32*t];
    }
    float m = v[0];
#pragma unroll
    for (int t = 1; t < 6; t++) m = fmaxf(m, v[t]);
#pragma unroll
    for (int o = 16; o; o >>= 1) m = fmaxf(m, __shfl_xor_sync(0xffffffffu, m, o));
    float s = 0.f;
#pragma unroll
    for (int t = 0; t < 6; t++) { v[t] = __expf(v[t] - m); s += v[t]; }
#pragma unroll
    for (int o = 16; o; o >>= 1) s += __shfl_xor_sync(0xffffffffu, s, o);
    const float inv = 1.0f / s;
#pragma unroll
    for (int t = 0; t < 3; t++) {
        pr[lane + 32*t] = v[t] * inv;
        pc[lane + 32*t] = v[3 + t] * inv;
    }
}

// ---------------- aggregation (bf16 MMA) ------------------------------------
// dst[n,c,r,a] = sum_b attn[n,r,a,b] * vsrc[n,c,r,b]
// GEMM per (n,r): M=512 (c), N=96 (a), K=96 (b); K split in two 48-tiles.
__global__ __launch_bounds__(256, 1)
void agg_mma(const float* __restrict__ attn, const __nv_bfloat16* __restrict__ vsrc,
             float* __restrict__ dst)
{
    __shared__ uint32_t Vs[128][28];     // [c][bpair] (24 used)
    __shared__ uint32_t Atts[96][28];    // [a][bpair]
    const int n = blockIdx.z, rr = blockIdx.y, c0 = blockIdx.x * 128;
    const int tid = threadIdx.x;
    const int warp = tid >> 5, lane = tid & 31;
    const int gid = lane >> 2, tig = lane & 3;
    const int wm = (warp >> 1) * 32;   // 4 warps along M (32 each)
    const int wn = (warp & 1) * 48;    // 2 warps along N (48 each)
    const long ab = (long)(n*96 + rr) * 96 * 96;
    const long vb = ((long)n * 512 + c0) * 9216 + (long)rr * 96;

    float acc[2][6][4];
#pragma unroll
    for (int mt = 0; mt < 2; mt++)
#pragma unroll
        for (int nt = 0; nt < 6; nt++)
#pragma unroll
            for (int i = 0; i < 4; i++) acc[mt][nt][i] = 0.f;

    for (int b0 = 0; b0 < 96; b0 += 48) {
        // V tile 128 x 48 bf16 (uint4 = 8 bf16 chunks)
#pragma unroll
        for (int i = tid; i < 128 * 6; i += 256) {
            int r = i / 6, ch = i % 6;
            uint4 u = *(const uint4*)&vsrc[vb + (long)r * 9216 + b0 + ch * 8];
            Vs[r][ch*4 + 0] = u.x; Vs[r][ch*4 + 1] = u.y;
            Vs[r][ch*4 + 2] = u.z; Vs[r][ch*4 + 3] = u.w;
        }
        // Att tile 96 x 48 (f32 -> bf16 pairs)
#pragma unroll
        for (int i = tid; i < 96 * 12; i += 256) {
            int a = i / 12, cp = i % 12;
            float4 f = *(const float4*)&attn[ab + (long)a * 96 + b0 + cp * 4];
            Atts[a][cp*2 + 0] = pack_bf2(f.x, f.y);
            Atts[a][cp*2 + 1] = pack_bf2(f.z, f.w);
        }
        __syncthreads();
#pragma unroll
        for (int ks = 0; ks < 3; ks++) {
            const int kk = ks * 8;
            uint32_t af[2][4], bf[6][2];
#pragma unroll
            for (int mt = 0; mt < 2; mt++) {
                int rb = wm + mt * 16;
                af[mt][0] = Vs[rb + gid    ][kk + tig];
                af[mt][1] = Vs[rb + gid + 8][kk + tig];
                af[mt][2] = Vs[rb + gid    ][kk + tig + 4];
                af[mt][3] = Vs[rb + gid + 8][kk + tig + 4];
            }
#pragma unroll
            for (int nt = 0; nt < 6; nt++) {
                int nb = wn + nt * 8;
                bf[nt][0] = Atts[nb + gid][kk + tig];
                bf[nt][1] = Atts[nb + gid][kk + tig + 4];
            }
#pragma unroll
            for (int mt = 0; mt < 2; mt++)
#pragma unroll
                for (int nt = 0; nt < 6; nt++)
                    mma_bf16(acc[mt][nt], af[mt][0], af[mt][1], af[mt][2], af[mt][3],
                             bf[nt][0], bf[nt][1]);
        }
        __syncthreads();
    }

    // epilogue: dst[((n*512+c)*96 + rr)*96 + a]
#pragma unroll
    for (int mt = 0; mt < 2; mt++) {
#pragma unroll
        for (int half = 0; half < 2; half++) {
            int c = c0 + wm + mt * 16 + gid + half * 8;
            float* drow = dst + (((long)n * 512 + c) * 96 + rr) * 96;
#pragma unroll
            for (int nt = 0; nt < 6; nt++) {
                int a = wn + nt * 8 + 2 * tig;
                float2 val;
                val.x = acc[mt][nt][half * 2 + 0];
                val.y = acc[mt][nt][half * 2 + 1];
                *(float2*)&drow[a] = val;
            }
        }
    }
}

// ---------------- finalize: out = gamma*(rowpart(out) + colT^T) + x ---------
__global__ __launch_bounds__(256)
void finalize_kernel(const float* __restrict__ colT, const float* __restrict__ x,
                     const float* __restrict__ gamma, float* __restrict__ out)
{
    __shared__ float t[32][33];
    const long base = (long)blockIdx.z * 9216;
    const int h0 = blockIdx.y * 32, w0 = blockIdx.x * 32;
    const int tx = threadIdx.x, ty0 = threadIdx.y;
#pragma unroll
    for (int i = ty0; i < 32; i += 8)
        t[i][tx] = colT[base + (long)(w0 + i) * 96 + h0 + tx];
    __syncthreads();
    const float g = gamma[0];
#pragma unroll
    for (int i = ty0; i < 32; i += 8) {
        long idx = base + (long)(h0 + i) * 96 + w0 + tx;
        out[idx] = g * (out[idx] + t[tx][i]) + x[idx];
    }
}

// ---------------- launch ----------------
extern "C" void kernel_launch(void* const* d_in, const int* in_sizes, int n_in,
                              void* d_out, int out_size)
{
    (void)in_sizes; (void)n_in; (void)out_size;
    const float* x     = (const float*)d_in[0];
    const float* wq    = (const float*)d_in[1];
    const float* bq    = (const float*)d_in[2];
    const float* wk    = (const float*)d_in[3];
    const float* bk    = (const float*)d_in[4];
    const float* wv    = (const float*)d_in[5];
    const float* bv    = (const float*)d_in[6];
    const float* gamma = (const float*)d_in[7];
    float* out = (float*)d_out;

    float *q, *k, *qT, *kT, *colT, *erow, *ecol, *B;
    __nv_bfloat16 *W, *xT, *vbf, *vTbf;
    cudaGetSymbolAddress((void**)&q,    g_q);
    cudaGetSymbolAddress((void**)&k,    g_k);
    cudaGetSymbolAddress((void**)&qT,   g_qT);
    cudaGetSymbolAddress((void**)&kT,   g_kT);
    cudaGetSymbolAddress((void**)&colT, g_colT);
    cudaGetSymbolAddress((void**)&erow, g_erow);
    cudaGetSymbolAddress((void**)&ecol, g_ecol);
    cudaGetSymbolAddress((void**)&B,    g_bpack);
    cudaGetSymbolAddress((void**)&W,    g_wbf);
    cudaGetSymbolAddress((void**)&xT,   g_xT);
    cudaGetSymbolAddress((void**)&vbf,  g_vbf);
    cudaGetSymbolAddress((void**)&vTbf, g_vTbf);

    // 0) pack weights -> bf16; convert+transpose x -> xT bf16
    pack_w<<<1280, 256>>>(wq, wk, wv, bq, bk, bv, W, B);
    xcvt_kernel<<<dim3(288, 16, 8), dim3(32, 8)>>>(x, xT);

    // 1) fused QKV projection (bf16 MMA, double-buffered cp.async)
    qkv_mma<<<dim3(72, 5, 8), 256>>>(W, B, xT, q, k, vbf);

    // 2) transposes (column-direction contiguity)
    transpose96<<<dim3(3,3,8*64),  dim3(32,8)>>>(q, qT);
    transpose96<<<dim3(3,3,8*64),  dim3(32,8)>>>(k, kT);
    transpose96_bf<<<dim3(3,3,8*512), dim3(32,8)>>>(vbf, vTbf);

    // 3) energies (f32)
    energy_kernel<false><<<dim3(96,8), 256>>>(q,  k,  erow);
    energy_kernel<true ><<<dim3(96,8), 256>>>(qT, kT, ecol);

    // 4) softmax over 192 (row||col) per pixel — in place
    softmax_kernel<<<9216, 256>>>(erow, ecol);

    // 5) aggregation (bf16 MMA)
    agg_mma<<<dim3(4,96,8), 256>>>(erow, vbf,  out);    // row part -> d_out
    agg_mma<<<dim3(4,96,8), 256>>>(ecol, vTbf, colT);   // col part -> colT

    // 6) finalize: out = gamma*(row + col) + x
    finalize_kernel<<<dim3(3,3,8*512), dim3(32,8)>>>(colT, x, gamma, out);
}

// round 13
// speedup vs baseline: 3.5703x; 1.0188x over previous
#include <cuda_runtime.h>
#include <cuda_bf16.h>
#include <cstdint>

#define NEGV (-1e30f)

// Problem constants: N=8, C=512, Cq=64, H=W=96

// ---------------- scratch (device globals; allocation-free) ----------------
__device__ float g_q   [8u*64*9216];          // [n,cq,h,w]
__device__ float g_k   [8u*64*9216];
__device__ float g_qT  [8u*64*9216];          // [n,cq,w,h]
__device__ float g_kT  [8u*64*9216];
__device__ float g_erow[8u*96*96*96];         // [n,h,w,v]
__device__ float g_ecol[8u*96*96*96];         // [n,w,h,j]
__device__ float g_bpack[640];
__device__ __nv_bfloat16 g_wbf  [640*512];     // packed [wq;wk;wv] bf16
__device__ __nv_bfloat16 g_xT   [8u*9216*512]; // x transposed [n,p,c] bf16
__device__ __nv_bfloat16 g_vbf  [8u*512*9216]; // v [n,c,h,w] bf16
__device__ __nv_bfloat16 g_vTbf [8u*512*9216]; // v [n,c,w,h] bf16
__device__ __nv_bfloat16 g_rowbf[8u*512*9216]; // row-attn out [n,c,h,w] bf16
__device__ __nv_bfloat16 g_colbf[8u*512*9216]; // col-attn out [n,c,w,h] bf16

// ---------------- helpers ----------------
__device__ __forceinline__ void mma_bf16(float c[4], uint32_t a0, uint32_t a1,
                                         uint32_t a2, uint32_t a3,
                                         uint32_t b0, uint32_t b1) {
    asm volatile(
        "mma.sync.aligned.m16n8k16.row.col.f32.bf16.bf16.f32 "
        "{%0,%1,%2,%3}, {%4,%5,%6,%7}, {%8,%9}, {%0,%1,%2,%3};"
        : "+f"(c[0]), "+f"(c[1]), "+f"(c[2]), "+f"(c[3])
        : "r"(a0), "r"(a1), "r"(a2), "r"(a3), "r"(b0), "r"(b1));
}

__device__ __forceinline__ uint32_t pack_bf2(float lo, float hi) {
    __nv_bfloat162 h = __floats2bfloat162_rn(lo, hi);   // h.x = lo
    return *(uint32_t*)&h;
}

__device__ __forceinline__ void cp_async16(uint32_t saddr, const void* gptr) {
    asm volatile("cp.async.cg.shared.global [%0], [%1], 16;" :: "r"(saddr), "l"(gptr));
}
__device__ __forceinline__ void cp_commit() { asm volatile("cp.async.commit_group;"); }
template<int N>
__device__ __forceinline__ void cp_wait() { asm volatile("cp.async.wait_group %0;" :: "n"(N)); }

// ---------------- weight packing (f32 -> bf16) ----------------
__global__ __launch_bounds__(256)
void pack_w(const float* __restrict__ wq, const float* __restrict__ wk,
            const float* __restrict__ wv, const float* __restrict__ bq,
            const float* __restrict__ bk, const float* __restrict__ bv,
            __nv_bfloat16* __restrict__ W, float* __restrict__ B)
{
    int idx = blockIdx.x * 256 + threadIdx.x;
    if (idx < 640 * 512) {
        int r = idx >> 9, c = idx & 511;
        float val = (r < 64) ? wq[r * 512 + c]
                  : (r < 128) ? wk[(r - 64) * 512 + c]
                              : wv[(r - 128) * 512 + c];
        W[idx] = __float2bfloat16(val);
    }
    if (idx < 640)
        B[idx] = (idx < 64) ? bq[idx] : (idx < 128) ? bk[idx - 64] : bv[idx - 128];
}

// ---------------- x convert+transpose: x[n,c,p] f32 -> xT[n,p,c] bf16 -------
__global__ __launch_bounds__(256)
void xcvt_kernel(const float* __restrict__ x, __nv_bfloat16* __restrict__ xT)
{
    __shared__ float t[32][33];
    const int n = blockIdx.z;
    const int c0 = blockIdx.y * 32, p0 = blockIdx.x * 32;
    const int tx = threadIdx.x, ty0 = threadIdx.y;
    const float* xn = x + (long)n * 512 * 9216;
#pragma unroll
    for (int i = ty0; i < 32; i += 8)
        t[i][tx] = xn[(long)(c0 + i) * 9216 + p0 + tx];
    __syncthreads();
    __nv_bfloat16* xTn = xT + (long)n * 9216 * 512;
#pragma unroll
    for (int i = ty0; i < 32; i += 8)
        xTn[(long)(p0 + i) * 512 + c0 + tx] = __float2bfloat16(t[tx][i]);
}

// ---------------- fused QKV projection (bf16 MMA, cp.async double-buffered) -
// Y[n, m, p] = sum_k W[m,k]*x[n,k,p] + bias[m];  m<64 -> q, <128 -> k, else vbf
__global__ __launch_bounds__(256, 1)
void qkv_mma(const __nv_bfloat16* __restrict__ W, const float* __restrict__ bias,
             const __nv_bfloat16* __restrict__ xT,
             float* __restrict__ q, float* __restrict__ k,
             __nv_bfloat16* __restrict__ vbf)
{
    __shared__ uint32_t As[2][128][20];   // [m][kpair] bf16 pairs; pitch 80B (16B-mult)
    __shared__ uint32_t Bs[2][128][20];   // [p][kpair]
    const int n = blockIdx.z;
    const int bm = blockIdx.y * 128, bn = blockIdx.x * 128;
    const int tid = threadIdx.x;
    const int warp = tid >> 5, lane = tid & 31;
    const int gid = lane >> 2, tig = lane & 3;
    const int wm = (warp >> 2) * 64;     // 2 warps along M
    const int wn = (warp & 3) * 32;      // 4 warps along N
    const __nv_bfloat16* xTn = xT + (long)n * 9216 * 512;

    const uint32_t as_base = (uint32_t)__cvta_generic_to_shared(&As[0][0][0]);
    const uint32_t bs_base = (uint32_t)__cvta_generic_to_shared(&Bs[0][0][0]);
    const int r  = tid >> 2, cc = tid & 3;          // chunk 0 mapping
    const int r2 = (tid + 256) >> 2, cc2 = (tid + 256) & 3;

    float acc[4][4][4];
#pragma unroll
    for (int mt = 0; mt < 4; mt++)
#pragma unroll
        for (int nt = 0; nt < 4; nt++)
#pragma unroll
            for (int i = 0; i < 4; i++) acc[mt][nt][i] = 0.f;

    // issue one 32-k tile (A+B) into buffer `buf`
    auto issue = [&](int k0, int buf) {
        cp_async16(as_base + (uint32_t)(((buf*128 + r )*20 + cc *4)*4),
                   &W  [(long)(bm + r ) * 512 + k0 + cc  * 8]);
        cp_async16(bs_base + (uint32_t)(((buf*128 + r )*20 + cc *4)*4),
                   &xTn[(long)(bn + r ) * 512 + k0 + cc  * 8]);
        cp_async16(as_base + (uint32_t)(((buf*128 + r2)*20 + cc2*4)*4),
                   &W  [(long)(bm + r2) * 512 + k0 + cc2 * 8]);
        cp_async16(bs_base + (uint32_t)(((buf*128 + r2)*20 + cc2*4)*4),
                   &xTn[(long)(bn + r2) * 512 + k0 + cc2 * 8]);
        cp_commit();
    };

    issue(0, 0);

    for (int t = 0; t < 16; t++) {
        if (t < 15) { issue((t + 1) * 32, (t + 1) & 1); cp_wait<1>(); }
        else        { cp_wait<0>(); }
        __syncthreads();
        const int buf = t & 1;
#pragma unroll
        for (int ks = 0; ks < 2; ks++) {
            const int kk = ks * 8;
            uint32_t af[4][4], bf[4][2];
#pragma unroll
            for (int mt = 0; mt < 4; mt++) {
                int rb = wm + mt * 16;
                af[mt][0] = As[buf][rb + gid    ][kk + tig];
                af[mt][1] = As[buf][rb + gid + 8][kk + tig];
                af[mt][2] = As[buf][rb + gid    ][kk + tig + 4];
                af[mt][3] = As[buf][rb + gid + 8][kk + tig + 4];
            }
#pragma unroll
            for (int nt = 0; nt < 4; nt++) {
                int nb = wn + nt * 8;
                bf[nt][0] = Bs[buf][nb + gid][kk + tig];
                bf[nt][1] = Bs[buf][nb + gid][kk + tig + 4];
            }
#pragma unroll
            for (int mt = 0; mt < 4; mt++)
#pragma unroll
                for (int nt = 0; nt < 4; nt++)
                    mma_bf16(acc[mt][nt], af[mt][0], af[mt][1], af[mt][2], af[mt][3],
                             bf[nt][0], bf[nt][1]);
        }
        __syncthreads();
    }

    // epilogue
#pragma unroll
    for (int mt = 0; mt < 4; mt++) {
#pragma unroll
        for (int half = 0; half < 2; half++) {
            int row = bm + wm + mt * 16 + gid + half * 8;
            float bi = bias[row];
            if (row < 128) {
                float* dst = (row < 64) ? q + ((long)n * 64 + row) * 9216
                                        : k + ((long)n * 64 + row - 64) * 9216;
#pragma unroll
                for (int nt = 0; nt < 4; nt++) {
                    int col = bn + wn + nt * 8 + 2 * tig;
                    float2 val;
                    val.x = acc[mt][nt][half * 2 + 0] + bi;
                    val.y = acc[mt][nt][half * 2 + 1] + bi;
                    *(float2*)&dst[col] = val;
                }
            } else {
                __nv_bfloat16* dst = vbf + ((long)n * 512 + row - 128) * 9216;
#pragma unroll
                for (int nt = 0; nt < 4; nt++) {
                    int col = bn + wn + nt * 8 + 2 * tig;
                    __nv_bfloat162 hv = __floats2bfloat162_rn(
                        acc[mt][nt][half * 2 + 0] + bi,
                        acc[mt][nt][half * 2 + 1] + bi);
                    *(__nv_bfloat162*)&dst[col] = hv;
                }
            }
        }
    }
}

// ---------------- transpose last two 96x96 dims (f32) ----------------
__global__ __launch_bounds__(256)
void transpose96(const float* __restrict__ in, float* __restrict__ out)
{
    __shared__ float t[32][33];
    const long base = (long)blockIdx.z * 9216;
    const int h0 = blockIdx.y * 32, w0 = blockIdx.x * 32;
    const int tx = threadIdx.x, ty0 = threadIdx.y;
#pragma unroll
    for (int i = ty0; i < 32; i += 8)
        t[i][tx] = in[base + (long)(h0 + i) * 96 + w0 + tx];
    __syncthreads();
#pragma unroll
    for (int i = ty0; i < 32; i += 8)
        out[base + (long)(w0 + i) * 96 + h0 + tx] = t[tx][i];
}

// ---------------- transpose last two 96x96 dims (bf16) ----------------
__global__ __launch_bounds__(256)
void transpose96_bf(const __nv_bfloat16* __restrict__ in, __nv_bfloat16* __restrict__ out)
{
    __shared__ __nv_bfloat16 t[32][33];
    const long base = (long)blockIdx.z * 9216;
    const int h0 = blockIdx.y * 32, w0 = blockIdx.x * 32;
    const int tx = threadIdx.x, ty0 = threadIdx.y;
#pragma unroll
    for (int i = ty0; i < 32; i += 8)
        t[i][tx] = in[base + (long)(h0 + i) * 96 + w0 + tx];
    __syncthreads();
#pragma unroll
    for (int i = ty0; i < 32; i += 8)
        out[base + (long)(w0 + i) * 96 + h0 + tx] = t[tx][i];
}

// ---------------- energies: e[a][b] = sum_c q[c][a]*k[c][b] per (n,r) -------
template<bool MASK>
__global__ __launch_bounds__(256)
void energy_kernel(const float* __restrict__ q, const float* __restrict__ k,
                   float* __restrict__ e)
{
    __shared__ float qs[64][96];
    __shared__ float ks[64][96];
    const int n = blockIdx.y, r = blockIdx.x;
    const int tid = threadIdx.x;
    const long qb = (long)n * 64 * 9216 + (long)r * 96;
#pragma unroll
    for (int i = tid; i < 64*96; i += 256) {
        int c = i / 96, p = i % 96;
        qs[c][p] = q[qb + (long)c * 9216 + p];
        ks[c][p] = k[qb + (long)c * 9216 + p];
    }
    __syncthreads();
    const int tx = tid % 16, ty = tid / 16;
    float acc[6][6];
#pragma unroll
    for (int i = 0; i < 6; i++)
#pragma unroll
        for (int j = 0; j < 6; j++) acc[i][j] = 0.f;
#pragma unroll 8
    for (int cc = 0; cc < 64; cc++) {
        float a[6], b[6];
#pragma unroll
        for (int i = 0; i < 6; i++) a[i] = qs[cc][ty*6 + i];
#pragma unroll
        for (int j = 0; j < 6; j++) b[j] = ks[cc][tx*6 + j];
#pragma unroll
        for (int i = 0; i < 6; i++)
#pragma unroll
            for (int j = 0; j < 6; j++)
                acc[i][j] = fmaf(a[i], b[j], acc[i][j]);
    }
    const long eb = (long)(n*96 + r) * 96 * 96;
#pragma unroll
    for (int i = 0; i < 6; i++) {
        int aa = ty*6 + i;
#pragma unroll
        for (int j = 0; j < 6; j++) {
            int bb = tx*6 + j;
            float vv = acc[i][j];
            if (MASK && aa == bb) vv = NEGV;
            e[eb + (long)aa * 96 + bb] = vv;
        }
    }
}

// ---------------- softmax over concat(row 96, col 96) per pixel -------------
__global__ __launch_bounds__(256)
void softmax_kernel(float* __restrict__ arow, float* __restrict__ acol)
{
    const int gtid = blockIdx.x * 256 + threadIdx.x;
    const int pix = gtid >> 5;
    const int lane = threadIdx.x & 31;
    const int n = pix / 9216, rem = pix % 9216;
    const int h = rem / 96, w = rem % 96;
    float* pr = arow + ((long)(n*96 + h) * 96 + w) * 96;
    float* pc = acol + ((long)(n*96 + w) * 96 + h) * 96;
    float v[6];
#pragma unroll
    for (int t = 0; t < 3; t++) {
        v[t]     = pr[lane + 32*t];
        v[3 + t] = pc[lane + 32*t];
    }
    float m = v[0];
#pragma unroll
    for (int t = 1; t < 6; t++) m = fmaxf(m, v[t]);
#pragma unroll
    for (int o = 16; o; o >>= 1) m = fmaxf(m, __shfl_xor_sync(0xffffffffu, m, o));
    float s = 0.f;
#pragma unroll
    for (int t = 0; t < 6; t++) { v[t] = __expf(v[t] - m); s += v[t]; }
#pragma unroll
    for (int o = 16; o; o >>= 1) s += __shfl_xor_sync(0xffffffffu, s, o);
    const float inv = 1.0f / s;
#pragma unroll
    for (int t = 0; t < 3; t++) {
        pr[lane + 32*t] = v[t] * inv;
        pc[lane + 32*t] = v[3 + t] * inv;
    }
}

// ---------------- aggregation (bf16 MMA, bf16 output) -----------------------
// dst[n,c,r,a] = sum_b attn[n,r,a,b] * vsrc[n,c,r,b]   (dst bf16)
// GEMM per (n,r): M=512 (c), N=96 (a), K=96 (b); K split in two 48-tiles.
__global__ __launch_bounds__(256, 1)
void agg_mma(const float* __restrict__ attn, const __nv_bfloat16* __restrict__ vsrc,
             __nv_bfloat16* __restrict__ dst)
{
    __shared__ uint32_t Vs[128][28];     // [c][bpair] (24 used)
    __shared__ uint32_t Atts[96][28];    // [a][bpair]
    const int n = blockIdx.z, rr = blockIdx.y, c0 = blockIdx.x * 128;
    const int tid = threadIdx.x;
    const int warp = tid >> 5, lane = tid & 31;
    const int gid = lane >> 2, tig = lane & 3;
    const int wm = (warp >> 1) * 32;   // 4 warps along M (32 each)
    const int wn = (warp & 1) * 48;    // 2 warps along N (48 each)
    const long ab = (long)(n*96 + rr) * 96 * 96;
    const long vb = ((long)n * 512 + c0) * 9216 + (long)rr * 96;

    float acc[2][6][4];
#pragma unroll
    for (int mt = 0; mt < 2; mt++)
#pragma unroll
        for (int nt = 0; nt < 6; nt++)
#pragma unroll
            for (int i = 0; i < 4; i++) acc[mt][nt][i] = 0.f;

    for (int b0 = 0; b0 < 96; b0 += 48) {
        // V tile 128 x 48 bf16 (uint4 = 8 bf16 chunks)
#pragma unroll
        for (int i = tid; i < 128 * 6; i += 256) {
            int r = i / 6, ch = i % 6;
            uint4 u = *(const uint4*)&vsrc[vb + (long)r * 9216 + b0 + ch * 8];
            Vs[r][ch*4 + 0] = u.x; Vs[r][ch*4 + 1] = u.y;
            Vs[r][ch*4 + 2] = u.z; Vs[r][ch*4 + 3] = u.w;
        }
        // Att tile 96 x 48 (f32 -> bf16 pairs)
#pragma unroll
        for (int i = tid; i < 96 * 12; i += 256) {
            int a = i / 12, cp = i % 12;
            float4 f = *(const float4*)&attn[ab + (long)a * 96 + b0 + cp * 4];
            Atts[a][cp*2 + 0] = pack_bf2(f.x, f.y);
            Atts[a][cp*2 + 1] = pack_bf2(f.z, f.w);
        }
        __syncthreads();
#pragma unroll
        for (int ks = 0; ks < 3; ks++) {
            const int kk = ks * 8;
            uint32_t af[2][4], bf[6][2];
#pragma unroll
            for (int mt = 0; mt < 2; mt++) {
                int rb = wm + mt * 16;
                af[mt][0] = Vs[rb + gid    ][kk + tig];
                af[mt][1] = Vs[rb + gid + 8][kk + tig];
                af[mt][2] = Vs[rb + gid    ][kk + tig + 4];
                af[mt][3] = Vs[rb + gid + 8][kk + tig + 4];
            }
#pragma unroll
            for (int nt = 0; nt < 6; nt++) {
                int nb = wn + nt * 8;
                bf[nt][0] = Atts[nb + gid][kk + tig];
                bf[nt][1] = Atts[nb + gid][kk + tig + 4];
            }
#pragma unroll
            for (int mt = 0; mt < 2; mt++)
#pragma unroll
                for (int nt = 0; nt < 6; nt++)
                    mma_bf16(acc[mt][nt], af[mt][0], af[mt][1], af[mt][2], af[mt][3],
                             bf[nt][0], bf[nt][1]);
        }
        __syncthreads();
    }

    // epilogue (bf16): dst[((n*512+c)*96 + rr)*96 + a]
#pragma unroll
    for (int mt = 0; mt < 2; mt++) {
#pragma unroll
        for (int half = 0; half < 2; half++) {
            int c = c0 + wm + mt * 16 + gid + half * 8;
            __nv_bfloat16* drow = dst + (((long)n * 512 + c) * 96 + rr) * 96;
#pragma unroll
            for (int nt = 0; nt < 6; nt++) {
                int a = wn + nt * 8 + 2 * tig;
                __nv_bfloat162 hv = __floats2bfloat162_rn(
                    acc[mt][nt][half * 2 + 0],
                    acc[mt][nt][half * 2 + 1]);
                *(__nv_bfloat162*)&drow[a] = hv;
            }
        }
    }
}

// ---------------- finalize: out = gamma*(rowbf + colbf^T) + x ---------------
__global__ __launch_bounds__(256)
void finalize_kernel(const __nv_bfloat16* __restrict__ rowp,
                     const __nv_bfloat16* __restrict__ colTp,
                     const float* __restrict__ x,
                     const float* __restrict__ gamma, float* __restrict__ out)
{
    __shared__ __nv_bfloat16 t[32][33];
    const long base = (long)blockIdx.z * 9216;
    const int h0 = blockIdx.y * 32, w0 = blockIdx.x * 32;
    const int tx = threadIdx.x, ty0 = threadIdx.y;
#pragma unroll
    for (int i = ty0; i < 32; i += 8)
        t[i][tx] = colTp[base + (long)(w0 + i) * 96 + h0 + tx];
    __syncthreads();
    const float g = gamma[0];
#pragma unroll
    for (int i = ty0; i < 32; i += 8) {
        long idx = base + (long)(h0 + i) * 96 + w0 + tx;
        float rowv = __bfloat162float(rowp[idx]);
        float colv = __bfloat162float(t[tx][i]);
        out[idx] = g * (rowv + colv) + x[idx];
    }
}

// ---------------- launch ----------------
extern "C" void kernel_launch(void* const* d_in, const int* in_sizes, int n_in,
                              void* d_out, int out_size)
{
    (void)in_sizes; (void)n_in; (void)out_size;
    const float* x     = (const float*)d_in[0];
    const float* wq    = (const float*)d_in[1];
    const float* bq    = (const float*)d_in[2];
    const float* wk    = (const float*)d_in[3];
    const float* bk    = (const float*)d_in[4];
    const float* wv    = (const float*)d_in[5];
    const float* bv    = (const float*)d_in[6];
    const float* gamma = (const float*)d_in[7];
    float* out = (float*)d_out;

    float *q, *k, *qT, *kT, *erow, *ecol, *B;
    __nv_bfloat16 *W, *xT, *vbf, *vTbf, *rowbf, *colbf;
    cudaGetSymbolAddress((void**)&q,     g_q);
    cudaGetSymbolAddress((void**)&k,     g_k);
    cudaGetSymbolAddress((void**)&qT,    g_qT);
    cudaGetSymbolAddress((void**)&kT,    g_kT);
    cudaGetSymbolAddress((void**)&erow,  g_erow);
    cudaGetSymbolAddress((void**)&ecol,  g_ecol);
    cudaGetSymbolAddress((void**)&B,     g_bpack);
    cudaGetSymbolAddress((void**)&W,     g_wbf);
    cudaGetSymbolAddress((void**)&xT,    g_xT);
    cudaGetSymbolAddress((void**)&vbf,   g_vbf);
    cudaGetSymbolAddress((void**)&vTbf,  g_vTbf);
    cudaGetSymbolAddress((void**)&rowbf, g_rowbf);
    cudaGetSymbolAddress((void**)&colbf, g_colbf);

    // 0) pack weights -> bf16; convert+transpose x -> xT bf16
    pack_w<<<1280, 256>>>(wq, wk, wv, bq, bk, bv, W, B);
    xcvt_kernel<<<dim3(288, 16, 8), dim3(32, 8)>>>(x, xT);

    // 1) fused QKV projection (bf16 MMA, double-buffered cp.async)
    qkv_mma<<<dim3(72, 5, 8), 256>>>(W, B, xT, q, k, vbf);

    // 2) transposes (column-direction contiguity)
    transpose96<<<dim3(3,3,8*64),  dim3(32,8)>>>(q, qT);
    transpose96<<<dim3(3,3,8*64),  dim3(32,8)>>>(k, kT);
    transpose96_bf<<<dim3(3,3,8*512), dim3(32,8)>>>(vbf, vTbf);

    // 3) energies (f32)
    energy_kernel<false><<<dim3(96,8), 256>>>(q,  k,  erow);
    energy_kernel<true ><<<dim3(96,8), 256>>>(qT, kT, ecol);

    // 4) softmax over 192 (row||col) per pixel — in place
    softmax_kernel<<<9216, 256>>>(erow, ecol);

    // 5) aggregation (bf16 MMA, bf16 outputs)
    agg_mma<<<dim3(4,96,8), 256>>>(erow, vbf,  rowbf);   // row part [n,c,h,w]
    agg_mma<<<dim3(4,96,8), 256>>>(ecol, vTbf, colbf);   // col part [n,c,w,h]

    // 6) finalize: out = gamma*(row + col^T) + x
    finalize_kernel<<<dim3(3,3,8*512), dim3(32,8)>>>(rowbf, colbf, x, gamma, out);
}

// round 16
// speedup vs baseline: 3.7358x; 1.0463x over previous
#include <cuda_runtime.h>
#include <cuda_bf16.h>
#include <cstdint>

#define NEGV (-1e30f)

// Problem constants: N=8, C=512, Cq=64, H=W=96

// ---------------- scratch (device globals; allocation-free) ----------------
__device__ float g_q   [8u*64*9216];          // [n,cq,h,w]
__device__ float g_k   [8u*64*9216];
__device__ float g_qT  [8u*64*9216];          // [n,cq,w,h]
__device__ float g_kT  [8u*64*9216];
__device__ float g_erow[8u*96*96*96];         // [n,h,w,v]
__device__ float g_ecol[8u*96*96*96];         // [n,w,h,j]
__device__ float g_bpack[640];
__device__ __nv_bfloat16 g_wbf  [640*512];     // packed [wq;wk;wv] bf16
__device__ __nv_bfloat16 g_vbf  [8u*512*9216]; // v [n,c,h,w] bf16
__device__ __nv_bfloat16 g_vTbf [8u*512*9216]; // v [n,c,w,h] bf16
__device__ __nv_bfloat16 g_rowbf[8u*512*9216]; // row-attn out [n,c,h,w] bf16
__device__ __nv_bfloat16 g_colbf[8u*512*9216]; // col-attn out [n,c,w,h] bf16

// ---------------- helpers ----------------
__device__ __forceinline__ void mma_bf16(float c[4], uint32_t a0, uint32_t a1,
                                         uint32_t a2, uint32_t a3,
                                         uint32_t b0, uint32_t b1) {
    asm volatile(
        "mma.sync.aligned.m16n8k16.row.col.f32.bf16.bf16.f32 "
        "{%0,%1,%2,%3}, {%4,%5,%6,%7}, {%8,%9}, {%0,%1,%2,%3};"
        : "+f"(c[0]), "+f"(c[1]), "+f"(c[2]), "+f"(c[3])
        : "r"(a0), "r"(a1), "r"(a2), "r"(a3), "r"(b0), "r"(b1));
}

__device__ __forceinline__ uint32_t pack_bf2(float lo, float hi) {
    __nv_bfloat162 h = __floats2bfloat162_rn(lo, hi);   // h.x = lo
    return *(uint32_t*)&h;
}

__device__ __forceinline__ void cp_async16(uint32_t saddr, const void* gptr) {
    asm volatile("cp.async.cg.shared.global [%0], [%1], 16;" :: "r"(saddr), "l"(gptr));
}
__device__ __forceinline__ void cp_commit() { asm volatile("cp.async.commit_group;"); }
template<int N>
__device__ __forceinline__ void cp_wait() { asm volatile("cp.async.wait_group %0;" :: "n"(N)); }

// ---------------- weight packing (f32 -> bf16) ----------------
__global__ __launch_bounds__(256)
void pack_w(const float* __restrict__ wq, const float* __restrict__ wk,
            const float* __restrict__ wv, const float* __restrict__ bq,
            const float* __restrict__ bk, const float* __restrict__ bv,
            __nv_bfloat16* __restrict__ W, float* __restrict__ B)
{
    int idx = blockIdx.x * 256 + threadIdx.x;
    if (idx < 640 * 512) {
        int r = idx >> 9, c = idx & 511;
        float val = (r < 64) ? wq[r * 512 + c]
                  : (r < 128) ? wk[(r - 64) * 512 + c]
                              : wv[(r - 128) * 512 + c];
        W[idx] = __float2bfloat16(val);
    }
    if (idx < 640)
        B[idx] = (idx < 64) ? bq[idx] : (idx < 128) ? bk[idx - 64] : bv[idx - 128];
}

// ---------------- fused QKV projection (bf16 MMA, direct f32 x reads) -------
// Y[n, m, p] = sum_k W[m,k]*x[n,k,p] + bias[m];  m<64 -> q, <128 -> k, else vbf
// A (weights) cp.async'd as bf16; B (x) cp.async'd as f32 tiles [32k x 128p],
// converted to bf16 fragments on the fly at fragment-load time.
__global__ __launch_bounds__(256, 1)
void qkv_mma(const __nv_bfloat16* __restrict__ W, const float* __restrict__ bias,
             const float* __restrict__ x,
             float* __restrict__ q, float* __restrict__ k,
             __nv_bfloat16* __restrict__ vbf)
{
    __shared__ uint32_t As[2][128][20];   // [m][kpair] bf16 pairs
    __shared__ float    Xs[2][32][132];   // [k][p] f32 staging (pad 132)
    const int n = blockIdx.z;
    const int bm = blockIdx.y * 128, bn = blockIdx.x * 128;
    const int tid = threadIdx.x;
    const int warp = tid >> 5, lane = tid & 31;
    const int gid = lane >> 2, tig = lane & 3;
    const int wm = (warp >> 2) * 64;     // 2 warps along M
    const int wn = (warp & 3) * 32;      // 4 warps along N
    const float* xn = x + (long)n * 512 * 9216;

    const uint32_t as_base = (uint32_t)__cvta_generic_to_shared(&As[0][0][0]);
    const uint32_t xs_base = (uint32_t)__cvta_generic_to_shared(&Xs[0][0][0]);
    const int r  = tid >> 2, cc = tid & 3;          // A chunk 0 mapping
    const int r2 = (tid + 256) >> 2, cc2 = (tid + 256) & 3;

    float acc[4][4][4];
#pragma unroll
    for (int mt = 0; mt < 4; mt++)
#pragma unroll
        for (int nt = 0; nt < 4; nt++)
#pragma unroll
            for (int i = 0; i < 4; i++) acc[mt][nt][i] = 0.f;

    // issue one 32-k tile (A bf16 + X f32) into buffer `buf`
    auto issue = [&](int k0, int buf) {
        cp_async16(as_base + (uint32_t)(((buf*128 + r )*20 + cc *4)*4),
                   &W[(long)(bm + r ) * 512 + k0 + cc  * 8]);
        cp_async16(as_base + (uint32_t)(((buf*128 + r2)*20 + cc2*4)*4),
                   &W[(long)(bm + r2) * 512 + k0 + cc2 * 8]);
#pragma unroll
        for (int t4 = 0; t4 < 4; t4++) {
            int ch = tid + t4 * 256;          // 1024 chunks: 32 rows x 32 float4
            int rr = ch >> 5, ccf = ch & 31;
            cp_async16(xs_base + (uint32_t)(((buf*32 + rr)*132 + ccf*4)*4),
                       &xn[(long)(k0 + rr) * 9216 + bn + ccf * 4]);
        }
        cp_commit();
    };

    issue(0, 0);

    for (int t = 0; t < 16; t++) {
        if (t < 15) { issue((t + 1) * 32, (t + 1) & 1); cp_wait<1>(); }
        else        { cp_wait<0>(); }
        __syncthreads();
        const int buf = t & 1;
#pragma unroll
        for (int ks = 0; ks < 2; ks++) {
            const int kk = ks * 8;
            uint32_t af[4][4], bf[4][2];
#pragma unroll
            for (int mt = 0; mt < 4; mt++) {
                int rb = wm + mt * 16;
                af[mt][0] = As[buf][rb + gid    ][kk + tig];
                af[mt][1] = As[buf][rb + gid + 8][kk + tig];
                af[mt][2] = As[buf][rb + gid    ][kk + tig + 4];
                af[mt][3] = As[buf][rb + gid + 8][kk + tig + 4];
            }
            const int ke0 = 2 * (kk + tig);       // k elements for frag reg 0
            const int ke1 = 2 * (kk + tig + 4);   // k elements for frag reg 1
#pragma unroll
            for (int nt = 0; nt < 4; nt++) {
                int p = wn + nt * 8 + gid;
                bf[nt][0] = pack_bf2(Xs[buf][ke0][p], Xs[buf][ke0 + 1][p]);
                bf[nt][1] = pack_bf2(Xs[buf][ke1][p], Xs[buf][ke1 + 1][p]);
            }
#pragma unroll
            for (int mt = 0; mt < 4; mt++)
#pragma unroll
                for (int nt = 0; nt < 4; nt++)
                    mma_bf16(acc[mt][nt], af[mt][0], af[mt][1], af[mt][2], af[mt][3],
                             bf[nt][0], bf[nt][1]);
        }
        __syncthreads();
    }

    // epilogue
#pragma unroll
    for (int mt = 0; mt < 4; mt++) {
#pragma unroll
        for (int half = 0; half < 2; half++) {
            int row = bm + wm + mt * 16 + gid + half * 8;
            float bi = bias[row];
            if (row < 128) {
                float* dst = (row < 64) ? q + ((long)n * 64 + row) * 9216
                                        : k + ((long)n * 64 + row - 64) * 9216;
#pragma unroll
                for (int nt = 0; nt < 4; nt++) {
                    int col = bn + wn + nt * 8 + 2 * tig;
                    float2 val;
                    val.x = acc[mt][nt][half * 2 + 0] + bi;
                    val.y = acc[mt][nt][half * 2 + 1] + bi;
                    *(float2*)&dst[col] = val;
                }
            } else {
                __nv_bfloat16* dst = vbf + ((long)n * 512 + row - 128) * 9216;
#pragma unroll
                for (int nt = 0; nt < 4; nt++) {
                    int col = bn + wn + nt * 8 + 2 * tig;
                    __nv_bfloat162 hv = __floats2bfloat162_rn(
                        acc[mt][nt][half * 2 + 0] + bi,
                        acc[mt][nt][half * 2 + 1] + bi);
                    *(__nv_bfloat162*)&dst[col] = hv;
                }
            }
        }
    }
}

// ---------------- transpose last two 96x96 dims (f32) ----------------
__global__ __launch_bounds__(256)
void transpose96(const float* __restrict__ in, float* __restrict__ out)
{
    __shared__ float t[32][33];
    const long base = (long)blockIdx.z * 9216;
    const int h0 = blockIdx.y * 32, w0 = blockIdx.x * 32;
    const int tx = threadIdx.x, ty0 = threadIdx.y;
#pragma unroll
    for (int i = ty0; i < 32; i += 8)
        t[i][tx] = in[base + (long)(h0 + i) * 96 + w0 + tx];
    __syncthreads();
#pragma unroll
    for (int i = ty0; i < 32; i += 8)
        out[base + (long)(w0 + i) * 96 + h0 + tx] = t[tx][i];
}

// ---------------- transpose last two 96x96 dims (bf16) ----------------
__global__ __launch_bounds__(256)
void transpose96_bf(const __nv_bfloat16* __restrict__ in, __nv_bfloat16* __restrict__ out)
{
    __shared__ __nv_bfloat16 t[32][33];
    const long base = (long)blockIdx.z * 9216;
    const int h0 = blockIdx.y * 32, w0 = blockIdx.x * 32;
    const int tx = threadIdx.x, ty0 = threadIdx.y;
#pragma unroll
    for (int i = ty0; i < 32; i += 8)
        t[i][tx] = in[base + (long)(h0 + i) * 96 + w0 + tx];
    __syncthreads();
#pragma unroll
    for (int i = ty0; i < 32; i += 8)
        out[base + (long)(w0 + i) * 96 + h0 + tx] = t[tx][i];
}

// ---------------- energies: e[a][b] = sum_c q[c][a]*k[c][b] per (n,r) -------
template<bool MASK>
__global__ __launch_bounds__(256)
void energy_kernel(const float* __restrict__ q, const float* __restrict__ k,
                   float* __restrict__ e)
{
    __shared__ float qs[64][96];
    __shared__ float ks[64][96];
    const int n = blockIdx.y, r = blockIdx.x;
    const int tid = threadIdx.x;
    const long qb = (long)n * 64 * 9216 + (long)r * 96;
#pragma unroll
    for (int i = tid; i < 64*96; i += 256) {
        int c = i / 96, p = i % 96;
        qs[c][p] = q[qb + (long)c * 9216 + p];
        ks[c][p] = k[qb + (long)c * 9216 + p];
    }
    __syncthreads();
    const int tx = tid % 16, ty = tid / 16;
    float acc[6][6];
#pragma unroll
    for (int i = 0; i < 6; i++)
#pragma unroll
        for (int j = 0; j < 6; j++) acc[i][j] = 0.f;
#pragma unroll 8
    for (int cc = 0; cc < 64; cc++) {
        float a[6], b[6];
#pragma unroll
        for (int i = 0; i < 6; i++) a[i] = qs[cc][ty*6 + i];
#pragma unroll
        for (int j = 0; j < 6; j++) b[j] = ks[cc][tx*6 + j];
#pragma unroll
        for (int i = 0; i < 6; i++)
#pragma unroll
            for (int j = 0; j < 6; j++)
                acc[i][j] = fmaf(a[i], b[j], acc[i][j]);
    }
    const long eb = (long)(n*96 + r) * 96 * 96;
#pragma unroll
    for (int i = 0; i < 6; i++) {
        int aa = ty*6 + i;
#pragma unroll
        for (int j = 0; j < 6; j++) {
            int bb = tx*6 + j;
            float vv = acc[i][j];
            if (MASK && aa == bb) vv = NEGV;
            e[eb + (long)aa * 96 + bb] = vv;
        }
    }
}

// ---------------- softmax over concat(row 96, col 96) per pixel -------------
__global__ __launch_bounds__(256)
void softmax_kernel(float* __restrict__ arow, float* __restrict__ acol)
{
    const int gtid = blockIdx.x * 256 + threadIdx.x;
    const int pix = gtid >> 5;
    const int lane = threadIdx.x & 31;
    const int n = pix / 9216, rem = pix % 9216;
    const int h = rem / 96, w = rem % 96;
    float* pr = arow + ((long)(n*96 + h) * 96 + w) * 96;
    float* pc = acol + ((long)(n*96 + w) * 96 + h) * 96;
    float v[6];
#pragma unroll
    for (int t = 0; t < 3; t++) {
        v[t]     = pr[lane + 32*t];
        v[3 + t] = pc[lane + 32*t];
    }
    float m = v[0];
#pragma unroll
    for (int t = 1; t < 6; t++) m = fmaxf(m, v[t]);
#pragma unroll
    for (int o = 16; o; o >>= 1) m = fmaxf(m, __shfl_xor_sync(0xffffffffu, m, o));
    float s = 0.f;
#pragma unroll
    for (int t = 0; t < 6; t++) { v[t] = __expf(v[t] - m); s += v[t]; }
#pragma unroll
    for (int o = 16; o; o >>= 1) s += __shfl_xor_sync(0xffffffffu, s, o);
    const float inv = 1.0f / s;
#pragma unroll
    for (int t = 0; t < 3; t++) {
        pr[lane + 32*t] = v[t] * inv;
        pc[lane + 32*t] = v[3 + t] * inv;
    }
}

// ---------------- aggregation (bf16 MMA, bf16 output) -----------------------
// dst[n,c,r,a] = sum_b attn[n,r,a,b] * vsrc[n,c,r,b]   (dst bf16)
__global__ __launch_bounds__(256, 1)
void agg_mma(const float* __restrict__ attn, const __nv_bfloat16* __restrict__ vsrc,
             __nv_bfloat16* __restrict__ dst)
{
    __shared__ uint32_t Vs[128][28];     // [c][bpair] (24 used)
    __shared__ uint32_t Atts[96][28];    // [a][bpair]
    const int n = blockIdx.z, rr = blockIdx.y, c0 = blockIdx.x * 128;
    const int tid = threadIdx.x;
    const int warp = tid >> 5, lane = tid & 31;
    const int gid = lane >> 2, tig = lane & 3;
    const int wm = (warp >> 1) * 32;   // 4 warps along M (32 each)
    const int wn = (warp & 1) * 48;    // 2 warps along N (48 each)
    const long ab = (long)(n*96 + rr) * 96 * 96;
    const long vb = ((long)n * 512 + c0) * 9216 + (long)rr * 96;

    float acc[2][6][4];
#pragma unroll
    for (int mt = 0; mt < 2; mt++)
#pragma unroll
        for (int nt = 0; nt < 6; nt++)
#pragma unroll
            for (int i = 0; i < 4; i++) acc[mt][nt][i] = 0.f;

    for (int b0 = 0; b0 < 96; b0 += 48) {
#pragma unroll
        for (int i = tid; i < 128 * 6; i += 256) {
            int r = i / 6, ch = i % 6;
            uint4 u = *(const uint4*)&vsrc[vb + (long)r * 9216 + b0 + ch * 8];
            Vs[r][ch*4 + 0] = u.x; Vs[r][ch*4 + 1] = u.y;
            Vs[r][ch*4 + 2] = u.z; Vs[r][ch*4 + 3] = u.w;
        }
#pragma unroll
        for (int i = tid; i < 96 * 12; i += 256) {
            int a = i / 12, cp = i % 12;
            float4 f = *(const float4*)&attn[ab + (long)a * 96 + b0 + cp * 4];
            Atts[a][cp*2 + 0] = pack_bf2(f.x, f.y);
            Atts[a][cp*2 + 1] = pack_bf2(f.z, f.w);
        }
        __syncthreads();
#pragma unroll
        for (int ks = 0; ks < 3; ks++) {
            const int kk = ks * 8;
            uint32_t af[2][4], bf[6][2];
#pragma unroll
            for (int mt = 0; mt < 2; mt++) {
                int rb = wm + mt * 16;
                af[mt][0] = Vs[rb + gid    ][kk + tig];
                af[mt][1] = Vs[rb + gid + 8][kk + tig];
                af[mt][2] = Vs[rb + gid    ][kk + tig + 4];
                af[mt][3] = Vs[rb + gid + 8][kk + tig + 4];
            }
#pragma unroll
            for (int nt = 0; nt < 6; nt++) {
                int nb = wn + nt * 8;
                bf[nt][0] = Atts[nb + gid][kk + tig];
                bf[nt][1] = Atts[nb + gid][kk + tig + 4];
            }
#pragma unroll
            for (int mt = 0; mt < 2; mt++)
#pragma unroll
                for (int nt = 0; nt < 6; nt++)
                    mma_bf16(acc[mt][nt], af[mt][0], af[mt][1], af[mt][2], af[mt][3],
                             bf[nt][0], bf[nt][1]);
        }
        __syncthreads();
    }

#pragma unroll
    for (int mt = 0; mt < 2; mt++) {
#pragma unroll
        for (int half = 0; half < 2; half++) {
            int c = c0 + wm + mt * 16 + gid + half * 8;
            __nv_bfloat16* drow = dst + (((long)n * 512 + c) * 96 + rr) * 96;
#pragma unroll
            for (int nt = 0; nt < 6; nt++) {
                int a = wn + nt * 8 + 2 * tig;
                __nv_bfloat162 hv = __floats2bfloat162_rn(
                    acc[mt][nt][half * 2 + 0],
                    acc[mt][nt][half * 2 + 1]);
                *(__nv_bfloat162*)&drow[a] = hv;
            }
        }
    }
}

// ---------------- finalize: out = gamma*(rowbf + colbf^T) + x ---------------
__global__ __launch_bounds__(256)
void finalize_kernel(const __nv_bfloat16* __restrict__ rowp,
                     const __nv_bfloat16* __restrict__ colTp,
                     const float* __restrict__ x,
                     const float* __restrict__ gamma, float* __restrict__ out)
{
    __shared__ __nv_bfloat16 t[32][33];
    const long base = (long)blockIdx.z * 9216;
    const int h0 = blockIdx.y * 32, w0 = blockIdx.x * 32;
    const int tx = threadIdx.x, ty0 = threadIdx.y;
#pragma unroll
    for (int i = ty0; i < 32; i += 8)
        t[i][tx] = colTp[base + (long)(w0 + i) * 96 + h0 + tx];
    __syncthreads();
    const float g = gamma[0];
#pragma unroll
    for (int i = ty0; i < 32; i += 8) {
        long idx = base + (long)(h0 + i) * 96 + w0 + tx;
        float rowv = __bfloat162float(rowp[idx]);
        float colv = __bfloat162float(t[tx][i]);
        out[idx] = g * (rowv + colv) + x[idx];
    }
}

// ---------------- launch ----------------
extern "C" void kernel_launch(void* const* d_in, const int* in_sizes, int n_in,
                              void* d_out, int out_size)
{
    (void)in_sizes; (void)n_in; (void)out_size;
    const float* x     = (const float*)d_in[0];
    const float* wq    = (const float*)d_in[1];
    const float* bq    = (const float*)d_in[2];
    const float* wk    = (const float*)d_in[3];
    const float* bk    = (const float*)d_in[4];
    const float* wv    = (const float*)d_in[5];
    const float* bv    = (const float*)d_in[6];
    const float* gamma = (const float*)d_in[7];
    float* out = (float*)d_out;

    float *q, *k, *qT, *kT, *erow, *ecol, *B;
    __nv_bfloat16 *W, *vbf, *vTbf, *rowbf, *colbf;
    cudaGetSymbolAddress((void**)&q,     g_q);
    cudaGetSymbolAddress((void**)&k,     g_k);
    cudaGetSymbolAddress((void**)&qT,    g_qT);
    cudaGetSymbolAddress((void**)&kT,    g_kT);
    cudaGetSymbolAddress((void**)&erow,  g_erow);
    cudaGetSymbolAddress((void**)&ecol,  g_ecol);
    cudaGetSymbolAddress((void**)&B,     g_bpack);
    cudaGetSymbolAddress((void**)&W,     g_wbf);
    cudaGetSymbolAddress((void**)&vbf,   g_vbf);
    cudaGetSymbolAddress((void**)&vTbf,  g_vTbf);
    cudaGetSymbolAddress((void**)&rowbf, g_rowbf);
    cudaGetSymbolAddress((void**)&colbf, g_colbf);

    // 0) pack weights -> bf16
    pack_w<<<1280, 256>>>(wq, wk, wv, bq, bk, bv, W, B);

    // 1) fused QKV projection (bf16 MMA, direct f32 x reads, double-buffered)
    qkv_mma<<<dim3(72, 5, 8), 256>>>(W, B, x, q, k, vbf);

    // 2) transposes (column-direction contiguity)
    transpose96<<<dim3(3,3,8*64),  dim3(32,8)>>>(q, qT);
    transpose96<<<dim3(3,3,8*64),  dim3(32,8)>>>(k, kT);
    transpose96_bf<<<dim3(3,3,8*512), dim3(32,8)>>>(vbf, vTbf);

    // 3) energies (f32)
    energy_kernel<false><<<dim3(96,8), 256>>>(q,  k,  erow);
    energy_kernel<true ><<<dim3(96,8), 256>>>(qT, kT, ecol);

    // 4) softmax over 192 (row||col) per pixel — in place
    softmax_kernel<<<9216, 256>>>(erow, ecol);

    // 5) aggregation (bf16 MMA, bf16 outputs)
    agg_mma<<<dim3(4,96,8), 256>>>(erow, vbf,  rowbf);   // row part [n,c,h,w]
    agg_mma<<<dim3(4,96,8), 256>>>(ecol, vTbf, colbf);   // col part [n,c,w,h]

    // 6) finalize: out = gamma*(row + col^T) + x
    finalize_kernel<<<dim3(3,3,8*512), dim3(32,8)>>>(rowbf, colbf, x, gamma, out);
}

// round 17
// speedup vs baseline: 4.1455x; 1.1097x over previous
#include <cuda_runtime.h>
#include <cuda_bf16.h>
#include <cstdint>

#define NEGV (-1e30f)

// Problem constants: N=8, C=512, Cq=64, H=W=96

// ---------------- scratch (device globals; allocation-free) ----------------
__device__ float g_q   [8u*64*9216];          // [n,cq,h,w]
__device__ float g_k   [8u*64*9216];
__device__ float g_qT  [8u*64*9216];          // [n,cq,w,h]
__device__ float g_kT  [8u*64*9216];
__device__ float g_erow[8u*96*96*96];         // [n,h,w,v]
__device__ float g_ecol[8u*96*96*96];         // [n,w,h,j]
__device__ float g_bpack[640];
__device__ __nv_bfloat16 g_wbf  [640*512];     // packed [wq;wk;wv] bf16
__device__ __nv_bfloat16 g_vbf  [8u*512*9216]; // v [n,c,h,w] bf16
__device__ __nv_bfloat16 g_vTbf [8u*512*9216]; // v [n,c,w,h] bf16
__device__ __nv_bfloat16 g_rowbf[8u*512*9216]; // row-attn out [n,c,h,w] bf16
__device__ __nv_bfloat16 g_colbf[8u*512*9216]; // col-attn out [n,c,w,h] bf16

// ---------------- helpers ----------------
__device__ __forceinline__ void mma_bf16(float c[4], uint32_t a0, uint32_t a1,
                                         uint32_t a2, uint32_t a3,
                                         uint32_t b0, uint32_t b1) {
    asm volatile(
        "mma.sync.aligned.m16n8k16.row.col.f32.bf16.bf16.f32 "
        "{%0,%1,%2,%3}, {%4,%5,%6,%7}, {%8,%9}, {%0,%1,%2,%3};"
        : "+f"(c[0]), "+f"(c[1]), "+f"(c[2]), "+f"(c[3])
        : "r"(a0), "r"(a1), "r"(a2), "r"(a3), "r"(b0), "r"(b1));
}

__device__ __forceinline__ uint32_t pack_bf2(float lo, float hi) {
    __nv_bfloat162 h = __floats2bfloat162_rn(lo, hi);   // h.x = lo
    return *(uint32_t*)&h;
}

__device__ __forceinline__ void cp_async16(uint32_t saddr, const void* gptr) {
    asm volatile("cp.async.cg.shared.global [%0], [%1], 16;" :: "r"(saddr), "l"(gptr));
}
__device__ __forceinline__ void cp_commit() { asm volatile("cp.async.commit_group;"); }
template<int N>
__device__ __forceinline__ void cp_wait() { asm volatile("cp.async.wait_group %0;" :: "n"(N)); }

// ---------------- weight packing (f32 -> bf16) ----------------
__global__ __launch_bounds__(256)
void pack_w(const float* __restrict__ wq, const float* __restrict__ wk,
            const float* __restrict__ wv, const float* __restrict__ bq,
            const float* __restrict__ bk, const float* __restrict__ bv,
            __nv_bfloat16* __restrict__ W, float* __restrict__ B)
{
    int idx = blockIdx.x * 256 + threadIdx.x;
    if (idx < 640 * 512) {
        int r = idx >> 9, c = idx & 511;
        float val = (r < 64) ? wq[r * 512 + c]
                  : (r < 128) ? wk[(r - 64) * 512 + c]
                              : wv[(r - 128) * 512 + c];
        W[idx] = __float2bfloat16(val);
    }
    if (idx < 640)
        B[idx] = (idx < 64) ? bq[idx] : (idx < 128) ? bk[idx - 64] : bv[idx - 128];
}

// ---------------- fused QKV projection (bf16 MMA, direct f32 x reads) -------
// Y[n, m, p] = sum_k W[m,k]*x[n,k,p] + bias[m];  m<64 -> q, <128 -> k, else vbf
// A (weights) cp.async'd as bf16; B (x) cp.async'd as f32 tiles [32k x 128p],
// converted to bf16 fragments on the fly at fragment-load time.
// launch_bounds(256,2): cap regs at 128 -> 2 CTAs/SM -> 16 warps for latency hiding.
__global__ __launch_bounds__(256, 2)
void qkv_mma(const __nv_bfloat16* __restrict__ W, const float* __restrict__ bias,
             const float* __restrict__ x,
             float* __restrict__ q, float* __restrict__ k,
             __nv_bfloat16* __restrict__ vbf)
{
    __shared__ uint32_t As[2][128][20];   // [m][kpair] bf16 pairs
    __shared__ float    Xs[2][32][132];   // [k][p] f32 staging (pad 132)
    const int n = blockIdx.z;
    const int bm = blockIdx.y * 128, bn = blockIdx.x * 128;
    const int tid = threadIdx.x;
    const int warp = tid >> 5, lane = tid & 31;
    const int gid = lane >> 2, tig = lane & 3;
    const int wm = (warp >> 2) * 64;     // 2 warps along M
    const int wn = (warp & 3) * 32;      // 4 warps along N
    const float* xn = x + (long)n * 512 * 9216;

    const uint32_t as_base = (uint32_t)__cvta_generic_to_shared(&As[0][0][0]);
    const uint32_t xs_base = (uint32_t)__cvta_generic_to_shared(&Xs[0][0][0]);
    const int r  = tid >> 2, cc = tid & 3;          // A chunk 0 mapping
    const int r2 = (tid + 256) >> 2, cc2 = (tid + 256) & 3;

    float acc[4][4][4];
#pragma unroll
    for (int mt = 0; mt < 4; mt++)
#pragma unroll
        for (int nt = 0; nt < 4; nt++)
#pragma unroll
            for (int i = 0; i < 4; i++) acc[mt][nt][i] = 0.f;

    // issue one 32-k tile (A bf16 + X f32) into buffer `buf`
    auto issue = [&](int k0, int buf) {
        cp_async16(as_base + (uint32_t)(((buf*128 + r )*20 + cc *4)*4),
                   &W[(long)(bm + r ) * 512 + k0 + cc  * 8]);
        cp_async16(as_base + (uint32_t)(((buf*128 + r2)*20 + cc2*4)*4),
                   &W[(long)(bm + r2) * 512 + k0 + cc2 * 8]);
#pragma unroll
        for (int t4 = 0; t4 < 4; t4++) {
            int ch = tid + t4 * 256;          // 1024 chunks: 32 rows x 32 float4
            int rr = ch >> 5, ccf = ch & 31;
            cp_async16(xs_base + (uint32_t)(((buf*32 + rr)*132 + ccf*4)*4),
                       &xn[(long)(k0 + rr) * 9216 + bn + ccf * 4]);
        }
        cp_commit();
    };

    issue(0, 0);

    for (int t = 0; t < 16; t++) {
        if (t < 15) { issue((t + 1) * 32, (t + 1) & 1); cp_wait<1>(); }
        else        { cp_wait<0>(); }
        __syncthreads();
        const int buf = t & 1;
#pragma unroll
        for (int ks = 0; ks < 2; ks++) {
            const int kk = ks * 8;
            uint32_t af[4][4], bf[4][2];
#pragma unroll
            for (int mt = 0; mt < 4; mt++) {
                int rb = wm + mt * 16;
                af[mt][0] = As[buf][rb + gid    ][kk + tig];
                af[mt][1] = As[buf][rb + gid + 8][kk + tig];
                af[mt][2] = As[buf][rb + gid    ][kk + tig + 4];
                af[mt][3] = As[buf][rb + gid + 8][kk + tig + 4];
            }
            const int ke0 = 2 * (kk + tig);       // k elements for frag reg 0
            const int ke1 = 2 * (kk + tig + 4);   // k elements for frag reg 1
#pragma unroll
            for (int nt = 0; nt < 4; nt++) {
                int p = wn + nt * 8 + gid;
                bf[nt][0] = pack_bf2(Xs[buf][ke0][p], Xs[buf][ke0 + 1][p]);
                bf[nt][1] = pack_bf2(Xs[buf][ke1][p], Xs[buf][ke1 + 1][p]);
            }
#pragma unroll
            for (int mt = 0; mt < 4; mt++)
#pragma unroll
                for (int nt = 0; nt < 4; nt++)
                    mma_bf16(acc[mt][nt], af[mt][0], af[mt][1], af[mt][2], af[mt][3],
                             bf[nt][0], bf[nt][1]);
        }
        __syncthreads();
    }

    // epilogue
#pragma unroll
    for (int mt = 0; mt < 4; mt++) {
#pragma unroll
        for (int half = 0; half < 2; half++) {
            int row = bm + wm + mt * 16 + gid + half * 8;
            float bi = bias[row];
            if (row < 128) {
                float* dst = (row < 64) ? q + ((long)n * 64 + row) * 9216
                                        : k + ((long)n * 64 + row - 64) * 9216;
#pragma unroll
                for (int nt = 0; nt < 4; nt++) {
                    int col = bn + wn + nt * 8 + 2 * tig;
                    float2 val;
                    val.x = acc[mt][nt][half * 2 + 0] + bi;
                    val.y = acc[mt][nt][half * 2 + 1] + bi;
                    *(float2*)&dst[col] = val;
                }
            } else {
                __nv_bfloat16* dst = vbf + ((long)n * 512 + row - 128) * 9216;
#pragma unroll
                for (int nt = 0; nt < 4; nt++) {
                    int col = bn + wn + nt * 8 + 2 * tig;
                    __nv_bfloat162 hv = __floats2bfloat162_rn(
                        acc[mt][nt][half * 2 + 0] + bi,
                        acc[mt][nt][half * 2 + 1] + bi);
                    *(__nv_bfloat162*)&dst[col] = hv;
                }
            }
        }
    }
}

// ---------------- transpose last two 96x96 dims (f32) ----------------
__global__ __launch_bounds__(256)
void transpose96(const float* __restrict__ in, float* __restrict__ out)
{
    __shared__ float t[32][33];
    const long base = (long)blockIdx.z * 9216;
    const int h0 = blockIdx.y * 32, w0 = blockIdx.x * 32;
    const int tx = threadIdx.x, ty0 = threadIdx.y;
#pragma unroll
    for (int i = ty0; i < 32; i += 8)
        t[i][tx] = in[base + (long)(h0 + i) * 96 + w0 + tx];
    __syncthreads();
#pragma unroll
    for (int i = ty0; i < 32; i += 8)
        out[base + (long)(w0 + i) * 96 + h0 + tx] = t[tx][i];
}

// ---------------- transpose last two 96x96 dims (bf16) ----------------
__global__ __launch_bounds__(256)
void transpose96_bf(const __nv_bfloat16* __restrict__ in, __nv_bfloat16* __restrict__ out)
{
    __shared__ __nv_bfloat16 t[32][33];
    const long base = (long)blockIdx.z * 9216;
    const int h0 = blockIdx.y * 32, w0 = blockIdx.x * 32;
    const int tx = threadIdx.x, ty0 = threadIdx.y;
#pragma unroll
    for (int i = ty0; i < 32; i += 8)
        t[i][tx] = in[base + (long)(h0 + i) * 96 + w0 + tx];
    __syncthreads();
#pragma unroll
    for (int i = ty0; i < 32; i += 8)
        out[base + (long)(w0 + i) * 96 + h0 + tx] = t[tx][i];
}

// ---------------- energies: e[a][b] = sum_c q[c][a]*k[c][b] per (n,r) -------
template<bool MASK>
__global__ __launch_bounds__(256)
void energy_kernel(const float* __restrict__ q, const float* __restrict__ k,
                   float* __restrict__ e)
{
    __shared__ float qs[64][96];
    __shared__ float ks[64][96];
    const int n = blockIdx.y, r = blockIdx.x;
    const int tid = threadIdx.x;
    const long qb = (long)n * 64 * 9216 + (long)r * 96;
#pragma unroll
    for (int i = tid; i < 64*96; i += 256) {
        int c = i / 96, p = i % 96;
        qs[c][p] = q[qb + (long)c * 9216 + p];
        ks[c][p] = k[qb + (long)c * 9216 + p];
    }
    __syncthreads();
    const int tx = tid % 16, ty = tid / 16;
    float acc[6][6];
#pragma unroll
    for (int i = 0; i < 6; i++)
#pragma unroll
        for (int j = 0; j < 6; j++) acc[i][j] = 0.f;
#pragma unroll 8
    for (int cc = 0; cc < 64; cc++) {
        float a[6], b[6];
#pragma unroll
        for (int i = 0; i < 6; i++) a[i] = qs[cc][ty*6 + i];
#pragma unroll
        for (int j = 0; j < 6; j++) b[j] = ks[cc][tx*6 + j];
#pragma unroll
        for (int i = 0; i < 6; i++)
#pragma unroll
            for (int j = 0; j < 6; j++)
                acc[i][j] = fmaf(a[i], b[j], acc[i][j]);
    }
    const long eb = (long)(n*96 + r) * 96 * 96;
#pragma unroll
    for (int i = 0; i < 6; i++) {
        int aa = ty*6 + i;
#pragma unroll
        for (int j = 0; j < 6; j++) {
            int bb = tx*6 + j;
            float vv = acc[i][j];
            if (MASK && aa == bb) vv = NEGV;
            e[eb + (long)aa * 96 + bb] = vv;
        }
    }
}

// ---------------- softmax over concat(row 96, col 96) per pixel -------------
__global__ __launch_bounds__(256)
void softmax_kernel(float* __restrict__ arow, float* __restrict__ acol)
{
    const int gtid = blockIdx.x * 256 + threadIdx.x;
    const int pix = gtid >> 5;
    const int lane = threadIdx.x & 31;
    const int n = pix / 9216, rem = pix % 9216;
    const int h = rem / 96, w = rem % 96;
    float* pr = arow + ((long)(n*96 + h) * 96 + w) * 96;
    float* pc = acol + ((long)(n*96 + w) * 96 + h) * 96;
    float v[6];
#pragma unroll
    for (int t = 0; t < 3; t++) {
        v[t]     = pr[lane + 32*t];
        v[3 + t] = pc[lane + 32*t];
    }
    float m = v[0];
#pragma unroll
    for (int t = 1; t < 6; t++) m = fmaxf(m, v[t]);
#pragma unroll
    for (int o = 16; o; o >>= 1) m = fmaxf(m, __shfl_xor_sync(0xffffffffu, m, o));
    float s = 0.f;
#pragma unroll
    for (int t = 0; t < 6; t++) { v[t] = __expf(v[t] - m); s += v[t]; }
#pragma unroll
    for (int o = 16; o; o >>= 1) s += __shfl_xor_sync(0xffffffffu, s, o);
    const float inv = 1.0f / s;
#pragma unroll
    for (int t = 0; t < 3; t++) {
        pr[lane + 32*t] = v[t] * inv;
        pc[lane + 32*t] = v[3 + t] * inv;
    }
}

// ---------------- aggregation (bf16 MMA, bf16 output) -----------------------
// dst[n,c,r,a] = sum_b attn[n,r,a,b] * vsrc[n,c,r,b]   (dst bf16)
__global__ __launch_bounds__(256, 1)
void agg_mma(const float* __restrict__ attn, const __nv_bfloat16* __restrict__ vsrc,
             __nv_bfloat16* __restrict__ dst)
{
    __shared__ uint32_t Vs[128][28];     // [c][bpair] (24 used)
    __shared__ uint32_t Atts[96][28];    // [a][bpair]
    const int n = blockIdx.z, rr = blockIdx.y, c0 = blockIdx.x * 128;
    const int tid = threadIdx.x;
    const int warp = tid >> 5, lane = tid & 31;
    const int gid = lane >> 2, tig = lane & 3;
    const int wm = (warp >> 1) * 32;   // 4 warps along M (32 each)
    const int wn = (warp & 1) * 48;    // 2 warps along N (48 each)
    const long ab = (long)(n*96 + rr) * 96 * 96;
    const long vb = ((long)n * 512 + c0) * 9216 + (long)rr * 96;

    float acc[2][6][4];
#pragma unroll
    for (int mt = 0; mt < 2; mt++)
#pragma unroll
        for (int nt = 0; nt < 6; nt++)
#pragma unroll
            for (int i = 0; i < 4; i++) acc[mt][nt][i] = 0.f;

    for (int b0 = 0; b0 < 96; b0 += 48) {
#pragma unroll
        for (int i = tid; i < 128 * 6; i += 256) {
            int r = i / 6, ch = i % 6;
            uint4 u = *(const uint4*)&vsrc[vb + (long)r * 9216 + b0 + ch * 8];
            Vs[r][ch*4 + 0] = u.x; Vs[r][ch*4 + 1] = u.y;
            Vs[r][ch*4 + 2] = u.z; Vs[r][ch*4 + 3] = u.w;
        }
#pragma unroll
        for (int i = tid; i < 96 * 12; i += 256) {
            int a = i / 12, cp = i % 12;
            float4 f = *(const float4*)&attn[ab + (long)a * 96 + b0 + cp * 4];
            Atts[a][cp*2 + 0] = pack_bf2(f.x, f.y);
            Atts[a][cp*2 + 1] = pack_bf2(f.z, f.w);
        }
        __syncthreads();
#pragma unroll
        for (int ks = 0; ks < 3; ks++) {
            const int kk = ks * 8;
            uint32_t af[2][4], bf[6][2];
#pragma unroll
            for (int mt = 0; mt < 2; mt++) {
                int rb = wm + mt * 16;
                af[mt][0] = Vs[rb + gid    ][kk + tig];
                af[mt][1] = Vs[rb + gid + 8][kk + tig];
                af[mt][2] = Vs[rb + gid    ][kk + tig + 4];
                af[mt][3] = Vs[rb + gid + 8][kk + tig + 4];
            }
#pragma unroll
            for (int nt = 0; nt < 6; nt++) {
                int nb = wn + nt * 8;
                bf[nt][0] = Atts[nb + gid][kk + tig];
                bf[nt][1] = Atts[nb + gid][kk + tig + 4];
            }
#pragma unroll
            for (int mt = 0; mt < 2; mt++)
#pragma unroll
                for (int nt = 0; nt < 6; nt++)
                    mma_bf16(acc[mt][nt], af[mt][0], af[mt][1], af[mt][2], af[mt][3],
                             bf[nt][0], bf[nt][1]);
        }
        __syncthreads();
    }

#pragma unroll
    for (int mt = 0; mt < 2; mt++) {
#pragma unroll
        for (int half = 0; half < 2; half++) {
            int c = c0 + wm + mt * 16 + gid + half * 8;
            __nv_bfloat16* drow = dst + (((long)n * 512 + c) * 96 + rr) * 96;
#pragma unroll
            for (int nt = 0; nt < 6; nt++) {
                int a = wn + nt * 8 + 2 * tig;
                __nv_bfloat162 hv = __floats2bfloat162_rn(
                    acc[mt][nt][half * 2 + 0],
                    acc[mt][nt][half * 2 + 1]);
                *(__nv_bfloat162*)&drow[a] = hv;
            }
        }
    }
}

// ---------------- finalize: out = gamma*(rowbf + colbf^T) + x ---------------
__global__ __launch_bounds__(256)
void finalize_kernel(const __nv_bfloat16* __restrict__ rowp,
                     const __nv_bfloat16* __restrict__ colTp,
                     const float* __restrict__ x,
                     const float* __restrict__ gamma, float* __restrict__ out)
{
    __shared__ __nv_bfloat16 t[32][33];
    const long base = (long)blockIdx.z * 9216;
    const int h0 = blockIdx.y * 32, w0 = blockIdx.x * 32;
    const int tx = threadIdx.x, ty0 = threadIdx.y;
#pragma unroll
    for (int i = ty0; i < 32; i += 8)
        t[i][tx] = colTp[base + (long)(w0 + i) * 96 + h0 + tx];
    __syncthreads();
    const float g = gamma[0];
#pragma unroll
    for (int i = ty0; i < 32; i += 8) {
        long idx = base + (long)(h0 + i) * 96 + w0 + tx;
        float rowv = __bfloat162float(rowp[idx]);
        float colv = __bfloat162float(t[tx][i]);
        out[idx] = g * (rowv + colv) + x[idx];
    }
}

// ---------------- launch ----------------
extern "C" void kernel_launch(void* const* d_in, const int* in_sizes, int n_in,
                              void* d_out, int out_size)
{
    (void)in_sizes; (void)n_in; (void)out_size;
    const float* x     = (const float*)d_in[0];
    const float* wq    = (const float*)d_in[1];
    const float* bq    = (const float*)d_in[2];
    const float* wk    = (const float*)d_in[3];
    const float* bk    = (const float*)d_in[4];
    const float* wv    = (const float*)d_in[5];
    const float* bv    = (const float*)d_in[6];
    const float* gamma = (const float*)d_in[7];
    float* out = (float*)d_out;

    float *q, *k, *qT, *kT, *erow, *ecol, *B;
    __nv_bfloat16 *W, *vbf, *vTbf, *rowbf, *colbf;
    cudaGetSymbolAddress((void**)&q,     g_q);
    cudaGetSymbolAddress((void**)&k,     g_k);
    cudaGetSymbolAddress((void**)&qT,    g_qT);
    cudaGetSymbolAddress((void**)&kT,    g_kT);
    cudaGetSymbolAddress((void**)&erow,  g_erow);
    cudaGetSymbolAddress((void**)&ecol,  g_ecol);
    cudaGetSymbolAddress((void**)&B,     g_bpack);
    cudaGetSymbolAddress((void**)&W,     g_wbf);
    cudaGetSymbolAddress((void**)&vbf,   g_vbf);
    cudaGetSymbolAddress((void**)&vTbf,  g_vTbf);
    cudaGetSymbolAddress((void**)&rowbf, g_rowbf);
    cudaGetSymbolAddress((void**)&colbf, g_colbf);

    // 0) pack weights -> bf16
    pack_w<<<1280, 256>>>(wq, wk, wv, bq, bk, bv, W, B);

    // 1) fused QKV projection (bf16 MMA, direct f32 x reads, double-buffered)
    qkv_mma<<<dim3(72, 5, 8), 256>>>(W, B, x, q, k, vbf);

    // 2) transposes (column-direction contiguity)
    transpose96<<<dim3(3,3,8*64),  dim3(32,8)>>>(q, qT);
    transpose96<<<dim3(3,3,8*64),  dim3(32,8)>>>(k, kT);
    transpose96_bf<<<dim3(3,3,8*512), dim3(32,8)>>>(vbf, vTbf);

    // 3) energies (f32)
    energy_kernel<false><<<dim3(96,8), 256>>>(q,  k,  erow);
    energy_kernel<true ><<<dim3(96,8), 256>>>(qT, kT, ecol);

    // 4) softmax over 192 (row||col) per pixel — in place
    softmax_kernel<<<9216, 256>>>(erow, ecol);

    // 5) aggregation (bf16 MMA, bf16 outputs)
    agg_mma<<<dim3(4,96,8), 256>>>(erow, vbf,  rowbf);   // row part [n,c,h,w]
    agg_mma<<<dim3(4,96,8), 256>>>(ecol, vTbf, colbf);   // col part [n,c,w,h]

    // 6) finalize: out = gamma*(row + col^T) + x
    finalize_kernel<<<dim3(3,3,8*512), dim3(32,8)>>>(rowbf, colbf, x, gamma, out);
}